// round 13
// baseline (speedup 1.0000x reference)
#include <cuda_runtime.h>
#include <cuda_fp16.h>
#include <math.h>

#define BB   64
#define LL   2048
#define VV   30
#define EE   128
#define GG   8
#define GEGE 1024
#define CC   64
#define FF   128
#define OO   30
#define NDND 9

#define XHP  36    // uint2 pitch per t-row, X hi slots (32 + pad; bank-stride 8)
#define ZFP  20    // uint2 pitch per t-row, Z hi slots (16 + pad; bank-stride 8)
#define RSCALE 2048.0f
#define RSCALE_INV 4.8828125e-4f

typedef unsigned int u32;

// ---------------- helpers ----------------------------------------------------
__device__ __forceinline__ void mma16816h(float* d, u32 a0, u32 a1, u32 a2, u32 a3,
                                          u32 b0, u32 b1) {
    asm volatile(
        "mma.sync.aligned.m16n8k16.row.col.f32.f16.f16.f32 "
        "{%0,%1,%2,%3}, {%4,%5,%6,%7}, {%8,%9}, {%0,%1,%2,%3};"
        : "+f"(d[0]), "+f"(d[1]), "+f"(d[2]), "+f"(d[3])
        : "r"(a0), "r"(a1), "r"(a2), "r"(a3), "r"(b0), "r"(b1));
}
__device__ __forceinline__ void split2h(float x0, float x1, u32& hi, u32& lo) {
    __half h0 = __float2half_rn(x0);
    __half h1 = __float2half_rn(x1);
    float r0 = (x0 - __half2float(h0)) * RSCALE;
    float r1 = (x1 - __half2float(h1)) * RSCALE;
    __half2 hv = __halves2half2(h0, h1);
    __half2 lv = __halves2half2(__float2half_rn(r0), __float2half_rn(r1));
    hi = *(u32*)&hv; lo = *(u32*)&lv;
}
__device__ __forceinline__ u32 pack2h(float x0, float x1) {
    __half2 hv = __halves2half2(__float2half_rn(x0), __float2half_rn(x1));
    return *(u32*)&hv;
}
__device__ __forceinline__ float2 recon2(u32 h, u32 l) {
    float2 a = __half22float2(*(__half2*)&h);
    float2 b = __half22float2(*(__half2*)&l);
    return make_float2(fmaf(b.x, RSCALE_INV, a.x), fmaf(b.y, RSCALE_INV, a.y));
}
__device__ __forceinline__ float fast_tanh(float x) {
    float e; asm("ex2.approx.f32 %0, %1;" : "=f"(e) : "f"(x * 2.8853900817779268f));
    float r; asm("rcp.approx.f32 %0, %1;" : "=f"(r) : "f"(e + 1.0f));
    return 1.0f - 2.0f * r;
}
__device__ __forceinline__ float fast_sigmoid(float x) {
    float e; asm("ex2.approx.f32 %0, %1;" : "=f"(e) : "f"(-x * 1.4426950408889634f));
    float r; asm("rcp.approx.f32 %0, %1;" : "=f"(r) : "f"(e + 1.0f));
    return r;
}

// ---------------- scratch -----------------------------------------------------
// residual in split-fp16 slot format: [sel][b][t][16 slots]; slot s holds
// channel pairs (qc, qc+4), qc = (s>>2)*8 + (s&3); H = fp16 hi, L = fp16 res*2048.
// Hi feeds the MMAs; hi+lo reconstructs the exact residual for the carry path.
__device__ uint2 g_rH[(size_t)3 * BB * LL * 16];
__device__ uint2 g_rL[(size_t)3 * BB * LL * 16];
__device__ float g_HF[NDND * BB * CC];
__device__ float g_HG[NDND * BB * CC];
__device__ float g_M0[VV * CC];
__device__ float g_M1[VV * CC];
__device__ u32 g_WF[NDND * 8192];
__device__ u32 g_WR[NDND * 2048];
__device__ u32 g_W1[4096];
__device__ u32 g_W2[2048];

__device__ __forceinline__ uint2* rowsH(int sel, int b) {
    return g_rH + ((size_t)sel * BB + b) * LL * 16;
}
__device__ __forceinline__ uint2* rowsL(int sel, int b) {
    return g_rL + ((size_t)sel * BB + b) * LL * 16;
}

// ---------------- K0a: fold embedding + initial conv ---------------------------
__global__ void __launch_bounds__(64) k_precompute_M(
    const float* __restrict__ emb, const float* __restrict__ wc)
{
    int v = blockIdx.x, c = threadIdx.x;
    float a0 = 0.f, a1 = 0.f;
    if (v != 0) {
        for (int e = 0; e < EE; e++) {
            float x = emb[v * EE + e];
            a0 = fmaf(x, wc[(c * EE + e) * 2 + 0], a0);
            a1 = fmaf(x, wc[(c * EE + e) * 2 + 1], a1);
        }
    }
    g_M0[v * CC + c] = a0;
    g_M1[v * CC + c] = a1;
}

// ---------------- K0b: all weights -> fp16 fragment layout ----------------------
__global__ void __launch_bounds__(256) k_prep(
    const float* __restrict__ wf, const float* __restrict__ wg,
    const float* __restrict__ wres,
    const float* __restrict__ w1, const float* __restrict__ w2)
{
    int layer = blockIdx.x;
    if (layer < NDND) {
        for (int idx = threadIdx.x; idx < 8192; idx += 256) {
            int w = idx >> 10, s = (idx >> 7) & 7;
            int lane = (idx >> 2) & 31, r = idx & 3;
            int m = w * 16 + (r & 1) * 8 + (lane >> 2);
            int k0 = s * 16 + ((r >> 1) & 1) * 8 + (lane & 3) * 2;
            const float* src = (m < 64) ? wf : wg;
            int cout = m & 63;
            int cin0 = k0 & 63, tap0 = k0 >> 6;
            int k1 = k0 + 1;
            int cin1 = k1 & 63, tap1 = k1 >> 6;
            float x0 = src[(((size_t)layer * 64 + cout) * 64 + cin0) * 2 + tap0];
            float x1 = src[(((size_t)layer * 64 + cout) * 64 + cin1) * 2 + tap1];
            g_WF[(size_t)layer * 8192 + idx] = pack2h(x0, x1);
        }
        for (int idx = threadIdx.x; idx < 2048; idx += 256) {
            int mt = idx >> 9, s = (idx >> 7) & 3;
            int lane = (idx >> 2) & 31, r = idx & 3;
            int m = mt * 16 + (r & 1) * 8 + (lane >> 2);
            int k0 = s * 16 + ((r >> 1) & 1) * 8 + (lane & 3) * 2;
            float x0 = wres[((size_t)layer * 64 + m) * 64 + k0];
            float x1 = wres[((size_t)layer * 64 + m) * 64 + k0 + 1];
            g_WR[(size_t)layer * 2048 + idx] = pack2h(x0, x1);
        }
    } else {
        for (int idx = threadIdx.x; idx < 4096; idx += 256) {
            int w = idx >> 9, s = (idx >> 7) & 3;
            int lane = (idx >> 2) & 31, r = idx & 3;
            int m = w * 16 + (r & 1) * 8 + (lane >> 2);
            int k0 = s * 16 + ((r >> 1) & 1) * 8 + (lane & 3) * 2;
            g_W1[idx] = pack2h(w1[m * 64 + k0], w1[m * 64 + k0 + 1]);
        }
        for (int idx = threadIdx.x; idx < 2048; idx += 256) {
            int mt = idx >> 10, s = (idx >> 7) & 7;
            int lane = (idx >> 2) & 31, r = idx & 3;
            int m = mt * 16 + (r & 1) * 8 + (lane >> 2);
            int k0 = s * 16 + ((r >> 1) & 1) * 8 + (lane & 3) * 2;
            float x0 = (m < OO) ? w2[m * 128 + k0] : 0.f;
            float x1 = (m < OO) ? w2[m * 128 + k0 + 1] : 0.f;
            g_W2[idx] = pack2h(x0, x1);
        }
    }
}

// ---------------- K2: conditioning vectors (embedding gather fused) -------------
__global__ void __launch_bounds__(256) k_H(
    const int* __restrict__ gin, const float* __restrict__ emb,
    const float* __restrict__ wlf, const float* __restrict__ blf,
    const float* __restrict__ wlg, const float* __restrict__ blg)
{
    __shared__ float sE[GEGE * 4];
    __shared__ float sR[256 * 4];
    int i = blockIdx.x;
    int b0 = blockIdx.y * 4;
    int tid = threadIdx.x;

    for (int idx = tid; idx < GEGE * 4; idx += 256) {
        int k = idx >> 2, bj = idx & 3;
        int g = k >> 7, e = k & 127;
        int tok = gin[(b0 + bj) * GG + g];
        sE[idx] = (tok == 0) ? 0.f : emb[tok * EE + e];
    }
    __syncthreads();

    int row = tid & 127;
    int half = tid >> 7;
    int c = row & 63;
    bool isf = row < 64;
    const float* w = (isf ? wlf : wlg) + ((size_t)i * CC + c) * GEGE + half * 512;
    const float* ep = sE + half * 512 * 4;

    float a0 = 0.f, a1 = 0.f, a2 = 0.f, a3 = 0.f;
    #pragma unroll 4
    for (int k = 0; k < 512; k += 4) {
        float4 wv = *(const float4*)(w + k);
        float4 e0 = *(const float4*)(ep + k * 4);
        float4 e1 = *(const float4*)(ep + k * 4 + 4);
        float4 e2 = *(const float4*)(ep + k * 4 + 8);
        float4 e3 = *(const float4*)(ep + k * 4 + 12);
        a0 = fmaf(wv.x, e0.x, a0); a1 = fmaf(wv.x, e0.y, a1);
        a2 = fmaf(wv.x, e0.z, a2); a3 = fmaf(wv.x, e0.w, a3);
        a0 = fmaf(wv.y, e1.x, a0); a1 = fmaf(wv.y, e1.y, a1);
        a2 = fmaf(wv.y, e1.z, a2); a3 = fmaf(wv.y, e1.w, a3);
        a0 = fmaf(wv.z, e2.x, a0); a1 = fmaf(wv.z, e2.y, a1);
        a2 = fmaf(wv.z, e2.z, a2); a3 = fmaf(wv.z, e2.w, a3);
        a0 = fmaf(wv.w, e3.x, a0); a1 = fmaf(wv.w, e3.y, a1);
        a2 = fmaf(wv.w, e3.z, a2); a3 = fmaf(wv.w, e3.w, a3);
    }
    *(float4*)&sR[tid * 4] = make_float4(a0, a1, a2, a3);
    __syncthreads();
    if (tid < 128) {
        float4 lo = *(const float4*)&sR[tid * 4];
        float4 hi = *(const float4*)&sR[(tid + 128) * 4];
        float bias = (isf ? blf : blg)[i * CC + c];
        float* dst = (isf ? g_HF : g_HG);
        dst[((size_t)i * BB + b0 + 0) * CC + c] = lo.x + hi.x + bias;
        dst[((size_t)i * BB + b0 + 1) * CC + c] = lo.y + hi.y + bias;
        dst[((size_t)i * BB + b0 + 2) * CC + c] = lo.z + hi.z + bias;
        dst[((size_t)i * BB + b0 + 3) * CC + c] = lo.w + hi.w + bias;
    }
}

// ---------------- K3: initial residual -> split slot format ----------------------
__global__ void __launch_bounds__(256) k_init(
    const int* __restrict__ tok, const float* __restrict__ b_causal)
{
    __shared__ float sM0[VV * CC], sM1[VV * CC], sb[CC];
    int tid = threadIdx.x;
    for (int i = tid; i < VV * CC; i += 256) { sM0[i] = g_M0[i]; sM1[i] = g_M1[i]; }
    if (tid < CC) sb[tid] = b_causal[tid];
    __syncthreads();
    int b = blockIdx.y, tt0 = blockIdx.x * 64;
    const int* tb = tok + b * LL;
    uint2* oH = rowsH(0, b);
    uint2* oL = rowsL(0, b);
    for (int idx = tid; idx < 1024; idx += 256) {
        int tl = idx >> 4, s = idx & 15;
        int qc = ((s >> 2) << 3) + (s & 3);
        int c0 = 2 * qc;
        int t = tt0 + tl;
        int v1 = tb[t] * CC;
        float r[4];
        r[0] = sM1[v1 + c0] + sb[c0];
        r[1] = sM1[v1 + c0 + 1] + sb[c0 + 1];
        r[2] = sM1[v1 + c0 + 8] + sb[c0 + 8];
        r[3] = sM1[v1 + c0 + 9] + sb[c0 + 9];
        if (t > 0) {
            int v0 = tb[t - 1] * CC;
            r[0] += sM0[v0 + c0];
            r[1] += sM0[v0 + c0 + 1];
            r[2] += sM0[v0 + c0 + 8];
            r[3] += sM0[v0 + c0 + 9];
        }
        u32 h1, l1, h2, l2;
        split2h(r[0], r[1], h1, l1);
        split2h(r[2], r[3], h2, l2);
        oH[t * 16 + s] = make_uint2(h1, h2);
        oL[t * 16 + s] = make_uint2(l1, l2);
    }
}

// ---------------- K4: dilated residual layer (hi-only MMAs, 80/warp) ------------
// SMEM (u32): XfH@0 (4608) | XfL@4608 (2048, cur-only) | Dsm@6656 (8704)
//             Zf@15360 (2560) | SK@17920 (4352) | biases@22272 (192) = 89856 B
__global__ void __launch_bounds__(256, 2) k_layer_tc(
    const float* __restrict__ b_f, const float* __restrict__ b_g,
    const float* __restrict__ b_res,
    int layer, int d, int in_sel, int out_sel)
{
    extern __shared__ u32 smem_u[];
    uint2* XfH = (uint2*)smem_u;                   // [t][sl] pitch XHP
    uint2* XfL = (uint2*)(smem_u + 4608);          // [t][s]  pitch 16 (cur rows only)
    float* Dsm = (float*)(smem_u + 6656);          // 128 x 68 f32
    uint2* Zf  = (uint2*)(smem_u + 15360);         // [t][sl] pitch ZFP
    float* SK  = (float*)(smem_u + 17920);         // 64 x 68 f32
    float* sBF = (float*)(smem_u + 22272);         // 64
    float* sBG = sBF + 64;                         // 64
    float* sBR = sBG + 64;                         // 64

    int tid = threadIdx.x;
    int lane = tid & 31;
    int w = tid >> 5;
    int b = blockIdx.y;
    int tt0 = blockIdx.x * 64;
    int r = lane & 3, tb = lane >> 2;

    if (tid < 64)
        sBF[tid] = b_f[layer * CC + tid] + g_HF[((size_t)layer * BB + b) * CC + tid];
    else if (tid < 128) {
        int c = tid - 64;
        sBG[c] = b_g[layer * CC + c] + g_HG[((size_t)layer * BB + b) * CC + c];
    } else if (tid < 192) {
        int c = tid - 128;
        sBR[c] = b_res[layer * CC + c];
    }

    // ---- X: hi slots for prev & cur; lo only for cur (epilogue reconstruct) ----
    const uint2* iH = rowsH(in_sel, b);
    const uint2* iL = rowsL(in_sel, b);
    #pragma unroll
    for (int it = 0; it < 8; it++) {
        int id = it * 256 + tid;          // 2048 slots
        int t = id >> 5;
        int sl = id & 31;
        int s = sl & 15;
        if (sl < 16) {
            int gt = tt0 + t - d;
            uint2 H = make_uint2(0u, 0u);
            if (gt >= 0) H = iH[gt * 16 + s];
            XfH[t * XHP + sl] = H;
        } else {
            int gt = tt0 + t;
            XfH[t * XHP + sl] = iH[gt * 16 + s];
            XfL[t * 16 + s] = iL[gt * 16 + s];
        }
    }
    __syncthreads();                      // (1) X ready

    // ---- GEMM1: 64 MMAs/warp, A via LDG register prefetch ----
    int mg = w & 3, ng = w >> 2;
    float acc[2][4][4];
    #pragma unroll
    for (int mi = 0; mi < 2; mi++)
        #pragma unroll
        for (int j = 0; j < 4; j++)
            #pragma unroll
            for (int rr = 0; rr < 4; rr++) acc[mi][j][rr] = 0.f;

    const uint4* WFp = (const uint4*)(g_WF + (size_t)layer * 8192) + (mg * 2) * 256;
    uint4 AhR[2][2];
    #pragma unroll
    for (int mi = 0; mi < 2; mi++) AhR[0][mi] = WFp[mi * 256 + lane];
    #pragma unroll
    for (int s = 0; s < 8; s++) {
        int cur = s & 1, nxt = cur ^ 1;
        if (s < 7) {
            #pragma unroll
            for (int mi = 0; mi < 2; mi++)
                AhR[nxt][mi] = WFp[mi * 256 + (s + 1) * 32 + lane];
        }
        uint2 B0 = XfH[(ng * 32 + 0 + tb) * XHP + s * 4 + r];
        uint2 B1 = XfH[(ng * 32 + 8 + tb) * XHP + s * 4 + r];
        uint2 B2 = XfH[(ng * 32 + 16 + tb) * XHP + s * 4 + r];
        uint2 B3 = XfH[(ng * 32 + 24 + tb) * XHP + s * 4 + r];
        #pragma unroll
        for (int mi = 0; mi < 2; mi++) {
            uint4 Ah = AhR[cur][mi];
            mma16816h(acc[mi][0], Ah.x, Ah.y, Ah.z, Ah.w, B0.x, B0.y);
            mma16816h(acc[mi][1], Ah.x, Ah.y, Ah.z, Ah.w, B1.x, B1.y);
            mma16816h(acc[mi][2], Ah.x, Ah.y, Ah.z, Ah.w, B2.x, B2.y);
            mma16816h(acc[mi][3], Ah.x, Ah.y, Ah.z, Ah.w, B3.x, B3.y);
        }
    }

    // ---- store D (Dsm separate; no barrier needed before store) ----
    {
        int gr = lane >> 2, tq = 2 * (lane & 3);
        #pragma unroll
        for (int mi = 0; mi < 2; mi++)
            #pragma unroll
            for (int j = 0; j < 4; j++) {
                int m = mg * 32 + mi * 16 + gr;
                int t = ng * 32 + j * 8 + tq;
                *(float2*)&Dsm[m * 68 + t] = make_float2(acc[mi][j][0], acc[mi][j][1]);
                *(float2*)&Dsm[(m + 8) * 68 + t] = make_float2(acc[mi][j][2], acc[mi][j][3]);
            }
    }
    __syncthreads();                      // (2) D ready

    // ---- gated activation -> Z hi slots ----
    #pragma unroll
    for (int it = 0; it < 4; it++) {
        int id = it * 256 + tid;
        int t = id >> 4;
        int sl = id & 15;
        int q = (sl >> 2) * 8 + (sl & 3);
        int c1 = 2 * q, c2 = 2 * q + 8;
        float f0 = Dsm[c1 * 68 + t] + sBF[c1];
        float f1 = Dsm[(c1 + 1) * 68 + t] + sBF[c1 + 1];
        float f2 = Dsm[c2 * 68 + t] + sBF[c2];
        float f3 = Dsm[(c2 + 1) * 68 + t] + sBF[c2 + 1];
        float g0 = Dsm[(c1 + 64) * 68 + t] + sBG[c1];
        float g1 = Dsm[(c1 + 65) * 68 + t] + sBG[c1 + 1];
        float g2 = Dsm[(c2 + 64) * 68 + t] + sBG[c2];
        float g3 = Dsm[(c2 + 65) * 68 + t] + sBG[c2 + 1];
        float z0 = fast_tanh(f0) * fast_sigmoid(g0);
        float z1 = fast_tanh(f1) * fast_sigmoid(g1);
        float z2 = fast_tanh(f2) * fast_sigmoid(g2);
        float z3 = fast_tanh(f3) * fast_sigmoid(g3);
        Zf[t * ZFP + sl] = make_uint2(pack2h(z0, z1), pack2h(z2, z3));
    }
    __syncthreads();                      // (3) Z ready

    // ---- GEMM2: 16 MMAs/warp ----
    int mg2 = w & 1, ng2 = w >> 1;
    float acc2[2][2][4];
    #pragma unroll
    for (int mi = 0; mi < 2; mi++)
        #pragma unroll
        for (int j = 0; j < 2; j++)
            #pragma unroll
            for (int rr = 0; rr < 4; rr++) acc2[mi][j][rr] = 0.f;

    const uint4* WRp = (const uint4*)(g_WR + (size_t)layer * 2048) + (mg2 * 2) * 128;
    uint4 Ah2R[2][2];
    #pragma unroll
    for (int mi = 0; mi < 2; mi++) Ah2R[0][mi] = WRp[mi * 128 + lane];
    #pragma unroll
    for (int s = 0; s < 4; s++) {
        int cur = s & 1, nxt = cur ^ 1;
        if (s < 3) {
            #pragma unroll
            for (int mi = 0; mi < 2; mi++)
                Ah2R[nxt][mi] = WRp[mi * 128 + (s + 1) * 32 + lane];
        }
        uint2 B0 = Zf[(ng2 * 16 + 0 + tb) * ZFP + s * 4 + r];
        uint2 B1 = Zf[(ng2 * 16 + 8 + tb) * ZFP + s * 4 + r];
        #pragma unroll
        for (int mi = 0; mi < 2; mi++) {
            uint4 Ah = Ah2R[cur][mi];
            mma16816h(acc2[mi][0], Ah.x, Ah.y, Ah.z, Ah.w, B0.x, B0.y);
            mma16816h(acc2[mi][1], Ah.x, Ah.y, Ah.z, Ah.w, B1.x, B1.y);
        }
    }

    // ---- store skip (separate buffer) ----
    {
        int gr = lane >> 2, tq = 2 * (lane & 3);
        #pragma unroll
        for (int mi = 0; mi < 2; mi++)
            #pragma unroll
            for (int j = 0; j < 2; j++) {
                int m = mg2 * 32 + mi * 16 + gr;
                int t = ng2 * 16 + j * 8 + tq;
                SK[t * 68 + m]       = acc2[mi][j][0];
                SK[(t + 1) * 68 + m] = acc2[mi][j][1];
                SK[t * 68 + m + 8]       = acc2[mi][j][2];
                SK[(t + 1) * 68 + m + 8] = acc2[mi][j][3];
            }
    }
    __syncthreads();                      // (4) SK ready

    // ---- epilogue: res_out = recon(XfH cur, XfL) + skip + b_res, re-split ----
    uint2* oH = rowsH(out_sel, b);
    uint2* oL = rowsL(out_sel, b);
    #pragma unroll
    for (int it = 0; it < 4; it++) {
        int id = it * 256 + tid;          // 1024 = 64t x 16 slots
        int t = id >> 4, s = id & 15;
        int qc = ((s >> 2) << 3) + (s & 3);
        int c0 = 2 * qc;
        uint2 H = XfH[t * XHP + 16 + s];
        uint2 L = XfL[t * 16 + s];
        float2 ra = recon2(H.x, L.x);     // channels c0, c0+1
        float2 rb = recon2(H.y, L.y);     // channels c0+8, c0+9
        float2 sk1 = *(const float2*)&SK[t * 68 + c0];
        float2 sk2 = *(const float2*)&SK[t * 68 + c0 + 8];
        float o0 = ra.x + sk1.x + sBR[c0];
        float o1 = ra.y + sk1.y + sBR[c0 + 1];
        float o2 = rb.x + sk2.x + sBR[c0 + 8];
        float o3 = rb.y + sk2.y + sBR[c0 + 9];
        u32 h1, l1, h2, l2;
        split2h(o0, o1, h1, l1);
        split2h(o2, o3, h2, l2);
        int gt = tt0 + t;
        oH[gt * 16 + s] = make_uint2(h1, h2);
        oL[gt * 16 + s] = make_uint2(l1, l2);
    }
}

// ---------------- K5: head (hi-only MMAs) ----------------------------------------
// SMEM (u32): XH@0 (2304; Dsm@0 overlay 8704) | HH@8704 (4352) = 52224 B
__global__ void __launch_bounds__(256, 2) k_final_tc(
    const float* __restrict__ b1, const float* __restrict__ b2,
    float* __restrict__ out)
{
    extern __shared__ u32 smem_u[];
    u32* XH = smem_u;                 // 64 x 36 u32
    float* Dsm = (float*)smem_u;      // overlay: 128 x 68 f32
    u32* HH = smem_u + 8704;          // 64 x 68 u32

    int tid = threadIdx.x;
    int lane = tid & 31;
    int w = tid >> 5;
    int b = blockIdx.y;
    int tt0 = blockIdx.x * 64;
    int tb = lane >> 2;

    const uint2* aH = rowsH(1, b);
    const uint2* aL = rowsL(1, b);
    const uint2* zH = rowsH(0, b);
    const uint2* zL = rowsL(0, b);
    #pragma unroll
    for (int it = 0; it < 4; it++) {
        int id = it * 256 + tid;          // 1024 = 64t x 16 slots
        int t = id >> 4, s = id & 15;
        int gt = tt0 + t;
        uint2 AH = aH[gt * 16 + s], AL = aL[gt * 16 + s];
        uint2 ZH0 = zH[gt * 16 + s], ZL0 = zL[gt * 16 + s];
        float2 a1 = recon2(AH.x, AL.x), a2 = recon2(AH.y, AL.y);
        float2 z1 = recon2(ZH0.x, ZL0.x), z2 = recon2(ZH0.y, ZL0.y);
        float s0 = fmaxf(a1.x - z1.x, 0.f), s1 = fmaxf(a1.y - z1.y, 0.f);
        float s2 = fmaxf(a2.x - z2.x, 0.f), s3 = fmaxf(a2.y - z2.y, 0.f);
        int q = ((s >> 2) << 3) + (s & 3);
        int o = t * 36 + q;
        XH[o] = pack2h(s0, s1);
        XH[o + 4] = pack2h(s2, s3);
    }
    __syncthreads();

    float acc[8][4];
    #pragma unroll
    for (int j = 0; j < 8; j++)
        #pragma unroll
        for (int rr = 0; rr < 4; rr++) acc[j][rr] = 0.f;

    const uint4* W1p = (const uint4*)(g_W1 + w * 512);
    #pragma unroll
    for (int s = 0; s < 4; s++) {
        uint4 Ah = W1p[s * 32 + lane];
        int kb = s * 8 + (lane & 3);
        #pragma unroll
        for (int j = 0; j < 8; j++) {
            int base = (j * 8 + tb) * 36 + kb;
            mma16816h(acc[j], Ah.x, Ah.y, Ah.z, Ah.w, XH[base], XH[base + 4]);
        }
    }
    __syncthreads();

    {
        int g = lane >> 2, tq = 2 * (lane & 3);
        int m = w * 16 + g;
        #pragma unroll
        for (int j = 0; j < 8; j++) {
            int t = j * 8 + tq;
            *(float2*)&Dsm[m * 68 + t] = make_float2(acc[j][0], acc[j][1]);
            *(float2*)&Dsm[(m + 8) * 68 + t] = make_float2(acc[j][2], acc[j][3]);
        }
    }
    __syncthreads();

    #pragma unroll
    for (int it = 0; it < 16; it++) {
        int id = it * 256 + tid;
        int mp = id & 63, t = id >> 6;
        float h0 = fmaxf(Dsm[(2 * mp) * 68 + t] + b1[2 * mp], 0.f);
        float h1 = fmaxf(Dsm[(2 * mp + 1) * 68 + t] + b1[2 * mp + 1], 0.f);
        HH[t * 68 + mp] = pack2h(h0, h1);
    }
    __syncthreads();

    int mt = w & 1;
    float acc2[2][4];
    #pragma unroll
    for (int j = 0; j < 2; j++)
        #pragma unroll
        for (int rr = 0; rr < 4; rr++) acc2[j][rr] = 0.f;

    const uint4* W2p = (const uint4*)(g_W2 + mt * 1024);
    #pragma unroll
    for (int s = 0; s < 8; s++) {
        uint4 Ah = W2p[s * 32 + lane];
        int kb = s * 8 + (lane & 3);
        #pragma unroll
        for (int j = 0; j < 2; j++) {
            int nblk = (w >> 1) * 2 + j;
            int base = (nblk * 8 + tb) * 68 + kb;
            mma16816h(acc2[j], Ah.x, Ah.y, Ah.z, Ah.w, HH[base], HH[base + 4]);
        }
    }

    {
        int m = mt * 16 + (lane >> 2);
        #pragma unroll
        for (int j = 0; j < 2; j++) {
            int nblk = (w >> 1) * 2 + j;
            int t = tt0 + nblk * 8 + 2 * (lane & 3);
            int o1 = m, o2 = m + 8;
            *(float2*)(out + ((size_t)b * OO + o1) * LL + t) =
                make_float2(acc2[j][0] + b2[o1], acc2[j][1] + b2[o1]);
            if (o2 < OO)
                *(float2*)(out + ((size_t)b * OO + o2) * LL + t) =
                    make_float2(acc2[j][2] + b2[o2], acc2[j][3] + b2[o2]);
        }
    }
}

// ---------------- launch ----------------------------------------------------------
extern "C" void kernel_launch(void* const* d_in, const int* in_sizes, int n_in,
                              void* d_out, int out_size)
{
    const int*   in_tok = (const int*)d_in[0];
    const int*   g_tok  = (const int*)d_in[1];
    const float* emb    = (const float*)d_in[2];
    const float* wc     = (const float*)d_in[3];
    const float* bc     = (const float*)d_in[4];
    const float* wf     = (const float*)d_in[5];
    const float* bf     = (const float*)d_in[6];
    const float* wg     = (const float*)d_in[7];
    const float* bg     = (const float*)d_in[8];
    const float* wlf    = (const float*)d_in[9];
    const float* blf    = (const float*)d_in[10];
    const float* wlg    = (const float*)d_in[11];
    const float* blg    = (const float*)d_in[12];
    const float* wres   = (const float*)d_in[13];
    const float* bres   = (const float*)d_in[14];
    const float* w1     = (const float*)d_in[15];
    const float* b1     = (const float*)d_in[16];
    const float* w2     = (const float*)d_in[17];
    const float* b2     = (const float*)d_in[18];
    float* out = (float*)d_out;

    const int LAYER_SMEM = 22464 * 4;   // 89856 B (2 blocks/SM)
    const int FINAL_SMEM = 13056 * 4;   // 52224 B
    cudaFuncSetAttribute(k_layer_tc, cudaFuncAttributeMaxDynamicSharedMemorySize, LAYER_SMEM);
    cudaFuncSetAttribute(k_final_tc, cudaFuncAttributeMaxDynamicSharedMemorySize, FINAL_SMEM);

    k_precompute_M<<<VV, 64>>>(emb, wc);
    k_prep<<<NDND + 1, 256>>>(wf, wg, wres, w1, w2);
    k_H<<<dim3(NDND, 16), 256>>>(g_tok, emb, wlf, blf, wlg, blg);
    k_init<<<dim3(LL / 64, BB), 256>>>(in_tok, bc);
    for (int i = 0; i < NDND; i++) {
        int d = 2 << i;
        int out_sel = (i % 2 == 0) ? 1 : 2;           // layer 8 -> sel 1
        int in_sel  = (i == 0) ? 0 : ((i % 2 == 0) ? 2 : 1);
        k_layer_tc<<<dim3(LL / 64, BB), 256, LAYER_SMEM>>>(
            bf, bg, bres, i, d, in_sel, out_sel);
    }
    k_final_tc<<<dim3(LL / 64, BB), 256, FINAL_SMEM>>>(b1, b2, out);
}

// round 14
// speedup vs baseline: 1.3611x; 1.3611x over previous
#include <cuda_runtime.h>
#include <cuda_fp16.h>
#include <math.h>

#define BB   64
#define LL   2048
#define VV   30
#define EE   128
#define GG   8
#define GEGE 1024
#define CC   64
#define FF   128
#define OO   30
#define NDND 9

#define XQ4  20    // uint4 pitch per t-row, X packed slots (16 + 4 pad)
#define ZQ4  12    // uint4 pitch per t-row, Z packed slots (8 + 4 pad)
#define RSCALE 2048.0f
#define RSCALE_INV 4.8828125e-4f

typedef unsigned int u32;

// ---------------- helpers ----------------------------------------------------
__device__ __forceinline__ void mma16816h(float* d, u32 a0, u32 a1, u32 a2, u32 a3,
                                          u32 b0, u32 b1) {
    asm volatile(
        "mma.sync.aligned.m16n8k16.row.col.f32.f16.f16.f32 "
        "{%0,%1,%2,%3}, {%4,%5,%6,%7}, {%8,%9}, {%0,%1,%2,%3};"
        : "+f"(d[0]), "+f"(d[1]), "+f"(d[2]), "+f"(d[3])
        : "r"(a0), "r"(a1), "r"(a2), "r"(a3), "r"(b0), "r"(b1));
}
__device__ __forceinline__ void split2h(float x0, float x1, u32& hi, u32& lo) {
    __half h0 = __float2half_rn(x0);
    __half h1 = __float2half_rn(x1);
    float r0 = (x0 - __half2float(h0)) * RSCALE;
    float r1 = (x1 - __half2float(h1)) * RSCALE;
    __half2 hv = __halves2half2(h0, h1);
    __half2 lv = __halves2half2(__float2half_rn(r0), __float2half_rn(r1));
    hi = *(u32*)&hv; lo = *(u32*)&lv;
}
__device__ __forceinline__ u32 pack2h(float x0, float x1) {
    __half2 hv = __halves2half2(__float2half_rn(x0), __float2half_rn(x1));
    return *(u32*)&hv;
}
__device__ __forceinline__ float2 recon2(u32 h, u32 l) {
    float2 a = __half22float2(*(__half2*)&h);
    float2 b = __half22float2(*(__half2*)&l);
    return make_float2(fmaf(b.x, RSCALE_INV, a.x), fmaf(b.y, RSCALE_INV, a.y));
}
__device__ __forceinline__ float fast_tanh(float x) {
    float e; asm("ex2.approx.f32 %0, %1;" : "=f"(e) : "f"(x * 2.8853900817779268f));
    float r; asm("rcp.approx.f32 %0, %1;" : "=f"(r) : "f"(e + 1.0f));
    return 1.0f - 2.0f * r;
}
__device__ __forceinline__ float fast_sigmoid(float x) {
    float e; asm("ex2.approx.f32 %0, %1;" : "=f"(e) : "f"(-x * 1.4426950408889634f));
    float r; asm("rcp.approx.f32 %0, %1;" : "=f"(r) : "f"(e + 1.0f));
    return r;
}

// ---------------- scratch -----------------------------------------------------
__device__ uint2 g_rH[(size_t)3 * BB * LL * 16];
__device__ uint2 g_rL[(size_t)3 * BB * LL * 16];
__device__ float g_HF[NDND * BB * CC];
__device__ float g_HG[NDND * BB * CC];
__device__ float g_M0[VV * CC];
__device__ float g_M1[VV * CC];
__device__ u32 g_WF[NDND * 8192];
__device__ u32 g_WR[NDND * 2048];
__device__ u32 g_W1[4096];
__device__ u32 g_W2[2048];

__device__ __forceinline__ uint2* rowsH(int sel, int b) {
    return g_rH + ((size_t)sel * BB + b) * LL * 16;
}
__device__ __forceinline__ uint2* rowsL(int sel, int b) {
    return g_rL + ((size_t)sel * BB + b) * LL * 16;
}

// ---------------- K0a: fold embedding + initial conv ---------------------------
__global__ void __launch_bounds__(64) k_precompute_M(
    const float* __restrict__ emb, const float* __restrict__ wc)
{
    int v = blockIdx.x, c = threadIdx.x;
    float a0 = 0.f, a1 = 0.f;
    if (v != 0) {
        for (int e = 0; e < EE; e++) {
            float x = emb[v * EE + e];
            a0 = fmaf(x, wc[(c * EE + e) * 2 + 0], a0);
            a1 = fmaf(x, wc[(c * EE + e) * 2 + 1], a1);
        }
    }
    g_M0[v * CC + c] = a0;
    g_M1[v * CC + c] = a1;
}

// ---------------- K0b: all weights -> fp16 fragment layout ----------------------
__global__ void __launch_bounds__(256) k_prep(
    const float* __restrict__ wf, const float* __restrict__ wg,
    const float* __restrict__ wres,
    const float* __restrict__ w1, const float* __restrict__ w2)
{
    int layer = blockIdx.x;
    if (layer < NDND) {
        for (int idx = threadIdx.x; idx < 8192; idx += 256) {
            int w = idx >> 10, s = (idx >> 7) & 7;
            int lane = (idx >> 2) & 31, r = idx & 3;
            int m = w * 16 + (r & 1) * 8 + (lane >> 2);
            int k0 = s * 16 + ((r >> 1) & 1) * 8 + (lane & 3) * 2;
            const float* src = (m < 64) ? wf : wg;
            int cout = m & 63;
            int cin0 = k0 & 63, tap0 = k0 >> 6;
            int k1 = k0 + 1;
            int cin1 = k1 & 63, tap1 = k1 >> 6;
            float x0 = src[(((size_t)layer * 64 + cout) * 64 + cin0) * 2 + tap0];
            float x1 = src[(((size_t)layer * 64 + cout) * 64 + cin1) * 2 + tap1];
            g_WF[(size_t)layer * 8192 + idx] = pack2h(x0, x1);
        }
        for (int idx = threadIdx.x; idx < 2048; idx += 256) {
            int mt = idx >> 9, s = (idx >> 7) & 3;
            int lane = (idx >> 2) & 31, r = idx & 3;
            int m = mt * 16 + (r & 1) * 8 + (lane >> 2);
            int k0 = s * 16 + ((r >> 1) & 1) * 8 + (lane & 3) * 2;
            float x0 = wres[((size_t)layer * 64 + m) * 64 + k0];
            float x1 = wres[((size_t)layer * 64 + m) * 64 + k0 + 1];
            g_WR[(size_t)layer * 2048 + idx] = pack2h(x0, x1);
        }
    } else {
        for (int idx = threadIdx.x; idx < 4096; idx += 256) {
            int w = idx >> 9, s = (idx >> 7) & 3;
            int lane = (idx >> 2) & 31, r = idx & 3;
            int m = w * 16 + (r & 1) * 8 + (lane >> 2);
            int k0 = s * 16 + ((r >> 1) & 1) * 8 + (lane & 3) * 2;
            g_W1[idx] = pack2h(w1[m * 64 + k0], w1[m * 64 + k0 + 1]);
        }
        for (int idx = threadIdx.x; idx < 2048; idx += 256) {
            int mt = idx >> 10, s = (idx >> 7) & 7;
            int lane = (idx >> 2) & 31, r = idx & 3;
            int m = mt * 16 + (r & 1) * 8 + (lane >> 2);
            int k0 = s * 16 + ((r >> 1) & 1) * 8 + (lane & 3) * 2;
            float x0 = (m < OO) ? w2[m * 128 + k0] : 0.f;
            float x1 = (m < OO) ? w2[m * 128 + k0 + 1] : 0.f;
            g_W2[idx] = pack2h(x0, x1);
        }
    }
}

// ---------------- K2: conditioning vectors (embedding gather fused) -------------
__global__ void __launch_bounds__(256) k_H(
    const int* __restrict__ gin, const float* __restrict__ emb,
    const float* __restrict__ wlf, const float* __restrict__ blf,
    const float* __restrict__ wlg, const float* __restrict__ blg)
{
    __shared__ float sE[GEGE * 4];
    __shared__ float sR[256 * 4];
    int i = blockIdx.x;
    int b0 = blockIdx.y * 4;
    int tid = threadIdx.x;

    for (int idx = tid; idx < GEGE * 4; idx += 256) {
        int k = idx >> 2, bj = idx & 3;
        int g = k >> 7, e = k & 127;
        int tok = gin[(b0 + bj) * GG + g];
        sE[idx] = (tok == 0) ? 0.f : emb[tok * EE + e];
    }
    __syncthreads();

    int row = tid & 127;
    int half = tid >> 7;
    int c = row & 63;
    bool isf = row < 64;
    const float* w = (isf ? wlf : wlg) + ((size_t)i * CC + c) * GEGE + half * 512;
    const float* ep = sE + half * 512 * 4;

    float a0 = 0.f, a1 = 0.f, a2 = 0.f, a3 = 0.f;
    #pragma unroll 4
    for (int k = 0; k < 512; k += 4) {
        float4 wv = *(const float4*)(w + k);
        float4 e0 = *(const float4*)(ep + k * 4);
        float4 e1 = *(const float4*)(ep + k * 4 + 4);
        float4 e2 = *(const float4*)(ep + k * 4 + 8);
        float4 e3 = *(const float4*)(ep + k * 4 + 12);
        a0 = fmaf(wv.x, e0.x, a0); a1 = fmaf(wv.x, e0.y, a1);
        a2 = fmaf(wv.x, e0.z, a2); a3 = fmaf(wv.x, e0.w, a3);
        a0 = fmaf(wv.y, e1.x, a0); a1 = fmaf(wv.y, e1.y, a1);
        a2 = fmaf(wv.y, e1.z, a2); a3 = fmaf(wv.y, e1.w, a3);
        a0 = fmaf(wv.z, e2.x, a0); a1 = fmaf(wv.z, e2.y, a1);
        a2 = fmaf(wv.z, e2.z, a2); a3 = fmaf(wv.z, e2.w, a3);
        a0 = fmaf(wv.w, e3.x, a0); a1 = fmaf(wv.w, e3.y, a1);
        a2 = fmaf(wv.w, e3.z, a2); a3 = fmaf(wv.w, e3.w, a3);
    }
    *(float4*)&sR[tid * 4] = make_float4(a0, a1, a2, a3);
    __syncthreads();
    if (tid < 128) {
        float4 lo = *(const float4*)&sR[tid * 4];
        float4 hi = *(const float4*)&sR[(tid + 128) * 4];
        float bias = (isf ? blf : blg)[i * CC + c];
        float* dst = (isf ? g_HF : g_HG);
        dst[((size_t)i * BB + b0 + 0) * CC + c] = lo.x + hi.x + bias;
        dst[((size_t)i * BB + b0 + 1) * CC + c] = lo.y + hi.y + bias;
        dst[((size_t)i * BB + b0 + 2) * CC + c] = lo.z + hi.z + bias;
        dst[((size_t)i * BB + b0 + 3) * CC + c] = lo.w + hi.w + bias;
    }
}

// ---------------- K3: initial residual -> split slot format ----------------------
__global__ void __launch_bounds__(256) k_init(
    const int* __restrict__ tok, const float* __restrict__ b_causal)
{
    __shared__ float sM0[VV * CC], sM1[VV * CC], sb[CC];
    int tid = threadIdx.x;
    for (int i = tid; i < VV * CC; i += 256) { sM0[i] = g_M0[i]; sM1[i] = g_M1[i]; }
    if (tid < CC) sb[tid] = b_causal[tid];
    __syncthreads();
    int b = blockIdx.y, tt0 = blockIdx.x * 64;
    const int* tb = tok + b * LL;
    uint2* oH = rowsH(0, b);
    uint2* oL = rowsL(0, b);
    for (int idx = tid; idx < 1024; idx += 256) {
        int tl = idx >> 4, s = idx & 15;
        int qc = ((s >> 2) << 3) + (s & 3);
        int c0 = 2 * qc;
        int t = tt0 + tl;
        int v1 = tb[t] * CC;
        float r[4];
        r[0] = sM1[v1 + c0] + sb[c0];
        r[1] = sM1[v1 + c0 + 1] + sb[c0 + 1];
        r[2] = sM1[v1 + c0 + 8] + sb[c0 + 8];
        r[3] = sM1[v1 + c0 + 9] + sb[c0 + 9];
        if (t > 0) {
            int v0 = tb[t - 1] * CC;
            r[0] += sM0[v0 + c0];
            r[1] += sM0[v0 + c0 + 1];
            r[2] += sM0[v0 + c0 + 8];
            r[3] += sM0[v0 + c0 + 9];
        }
        u32 h1, l1, h2, l2;
        split2h(r[0], r[1], h1, l1);
        split2h(r[2], r[3], h2, l2);
        oH[t * 16 + s] = make_uint2(h1, h2);
        oL[t * 16 + s] = make_uint2(l1, l2);
    }
}

// ---------------- K4: dilated residual layer (hi-only, packed uint4 B) ----------
// SMEM (u32): Xq@0 (5120) | XfL@5120 (2048) | Dsm@7168 (8704)
//             Zq@15872 (3072) | SK@18944 (4352) | biases@23296 (192) = 93952 B
// Xq[t][j] (j = s*4+r, pitch XQ4): (prevH_s_pair, curH_{s+4}_pair) -> one LDS.128
// feeds k-steps s (.xy) and s+4 (.zw).  Zq analogous with (s, s+2).
__global__ void __launch_bounds__(256, 2) k_layer_tc(
    const float* __restrict__ b_f, const float* __restrict__ b_g,
    const float* __restrict__ b_res,
    int layer, int d, int in_sel, int out_sel)
{
    extern __shared__ u32 smem_u[];
    uint4* Xq  = (uint4*)smem_u;                   // 64 x XQ4
    uint2* XfL = (uint2*)(smem_u + 5120);          // [t][j] pitch 16 (cur lo)
    float* Dsm = (float*)(smem_u + 7168);          // 128 x 68
    uint4* Zq  = (uint4*)(smem_u + 15872);         // 64 x ZQ4
    float* SK  = (float*)(smem_u + 18944);         // 64 x 68
    float* sBF = (float*)(smem_u + 23296);         // 64
    float* sBG = sBF + 64;
    float* sBR = sBG + 64;

    int tid = threadIdx.x;
    int lane = tid & 31;
    int w = tid >> 5;
    int b = blockIdx.y;
    int tt0 = blockIdx.x * 64;
    int r = lane & 3, tb = lane >> 2;

    if (tid < 64)
        sBF[tid] = b_f[layer * CC + tid] + g_HF[((size_t)layer * BB + b) * CC + tid];
    else if (tid < 128) {
        int c = tid - 64;
        sBG[c] = b_g[layer * CC + c] + g_HG[((size_t)layer * BB + b) * CC + c];
    } else if (tid < 192) {
        int c = tid - 128;
        sBR[c] = b_res[layer * CC + c];
    }

    // ---- build Xq: prev-hi in .xy, cur-hi in .zw; cur-lo in XfL ----
    const uint2* iH = rowsH(in_sel, b);
    const uint2* iL = rowsL(in_sel, b);
    #pragma unroll
    for (int it = 0; it < 4; it++) {
        int id = it * 256 + tid;          // 1024 = 64t x 16 j
        int t = id >> 4, j = id & 15;
        int gtp = tt0 + t - d;
        int gtc = tt0 + t;
        uint2 P = make_uint2(0u, 0u);
        if (gtp >= 0) P = iH[gtp * 16 + j];
        uint2 C = iH[gtc * 16 + j];
        Xq[t * XQ4 + j] = make_uint4(P.x, P.y, C.x, C.y);
        XfL[t * 16 + j] = iL[gtc * 16 + j];
    }
    __syncthreads();                      // (1) X ready

    // ---- GEMM1: 64 MMAs/warp, one LDS.128 per 2 k-steps ----
    int mg = w & 3, ng = w >> 2;
    float acc[2][4][4];
    #pragma unroll
    for (int mi = 0; mi < 2; mi++)
        #pragma unroll
        for (int j = 0; j < 4; j++)
            #pragma unroll
            for (int rr = 0; rr < 4; rr++) acc[mi][j][rr] = 0.f;

    const uint4* WFp = (const uint4*)(g_WF + (size_t)layer * 8192) + (mg * 2) * 256;
    uint4 A[2][2][2];   // [buf][mi][half]
    #pragma unroll
    for (int mi = 0; mi < 2; mi++) {
        A[0][mi][0] = WFp[mi * 256 + lane];              // s = 0
        A[0][mi][1] = WFp[mi * 256 + 4 * 32 + lane];     // s = 4
    }
    #pragma unroll
    for (int s = 0; s < 4; s++) {
        int cur = s & 1, nxt = cur ^ 1;
        if (s < 3) {
            #pragma unroll
            for (int mi = 0; mi < 2; mi++) {
                A[nxt][mi][0] = WFp[mi * 256 + (s + 1) * 32 + lane];
                A[nxt][mi][1] = WFp[mi * 256 + (s + 5) * 32 + lane];
            }
        }
        uint4 B0 = Xq[(ng * 32 + 0 + tb) * XQ4 + s * 4 + r];
        uint4 B1 = Xq[(ng * 32 + 8 + tb) * XQ4 + s * 4 + r];
        uint4 B2 = Xq[(ng * 32 + 16 + tb) * XQ4 + s * 4 + r];
        uint4 B3 = Xq[(ng * 32 + 24 + tb) * XQ4 + s * 4 + r];
        #pragma unroll
        for (int mi = 0; mi < 2; mi++) {
            uint4 a0 = A[cur][mi][0];
            uint4 a1 = A[cur][mi][1];
            mma16816h(acc[mi][0], a0.x, a0.y, a0.z, a0.w, B0.x, B0.y);
            mma16816h(acc[mi][0], a1.x, a1.y, a1.z, a1.w, B0.z, B0.w);
            mma16816h(acc[mi][1], a0.x, a0.y, a0.z, a0.w, B1.x, B1.y);
            mma16816h(acc[mi][1], a1.x, a1.y, a1.z, a1.w, B1.z, B1.w);
            mma16816h(acc[mi][2], a0.x, a0.y, a0.z, a0.w, B2.x, B2.y);
            mma16816h(acc[mi][2], a1.x, a1.y, a1.z, a1.w, B2.z, B2.w);
            mma16816h(acc[mi][3], a0.x, a0.y, a0.z, a0.w, B3.x, B3.y);
            mma16816h(acc[mi][3], a1.x, a1.y, a1.z, a1.w, B3.z, B3.w);
        }
    }

    // ---- store D (separate buffer) ----
    {
        int gr = lane >> 2, tq = 2 * (lane & 3);
        #pragma unroll
        for (int mi = 0; mi < 2; mi++)
            #pragma unroll
            for (int j = 0; j < 4; j++) {
                int m = mg * 32 + mi * 16 + gr;
                int t = ng * 32 + j * 8 + tq;
                *(float2*)&Dsm[m * 68 + t] = make_float2(acc[mi][j][0], acc[mi][j][1]);
                *(float2*)&Dsm[(m + 8) * 68 + t] = make_float2(acc[mi][j][2], acc[mi][j][3]);
            }
    }
    __syncthreads();                      // (2) D ready

    // ---- gated activation -> Zq halves ----
    #pragma unroll
    for (int it = 0; it < 4; it++) {
        int id = it * 256 + tid;          // 1024 = 64t x 16 slots
        int t = id >> 4;
        int sl = id & 15;
        int s = sl >> 2, rr2 = sl & 3;
        int q = s * 8 + rr2;              // kpair index
        int c1 = 2 * q, c2 = 2 * q + 8;
        float f0 = Dsm[c1 * 68 + t] + sBF[c1];
        float f1 = Dsm[(c1 + 1) * 68 + t] + sBF[c1 + 1];
        float f2 = Dsm[c2 * 68 + t] + sBF[c2];
        float f3 = Dsm[(c2 + 1) * 68 + t] + sBF[c2 + 1];
        float g0 = Dsm[(c1 + 64) * 68 + t] + sBG[c1];
        float g1 = Dsm[(c1 + 65) * 68 + t] + sBG[c1 + 1];
        float g2 = Dsm[(c2 + 64) * 68 + t] + sBG[c2];
        float g3 = Dsm[(c2 + 65) * 68 + t] + sBG[c2 + 1];
        float z0 = fast_tanh(f0) * fast_sigmoid(g0);
        float z1 = fast_tanh(f1) * fast_sigmoid(g1);
        float z2 = fast_tanh(f2) * fast_sigmoid(g2);
        float z3 = fast_tanh(f3) * fast_sigmoid(g3);
        int j2 = (s & 1) * 4 + rr2;
        int half = s >> 1;
        *(uint2*)(smem_u + 15872 + t * (ZQ4 * 4) + j2 * 4 + half * 2) =
            make_uint2(pack2h(z0, z1), pack2h(z2, z3));
    }
    __syncthreads();                      // (3) Z ready

    // ---- GEMM2: 16 MMAs/warp ----
    int mg2 = w & 1, ng2 = w >> 1;
    float acc2[2][2][4];
    #pragma unroll
    for (int mi = 0; mi < 2; mi++)
        #pragma unroll
        for (int j = 0; j < 2; j++)
            #pragma unroll
            for (int rr = 0; rr < 4; rr++) acc2[mi][j][rr] = 0.f;

    const uint4* WRp = (const uint4*)(g_WR + (size_t)layer * 2048) + (mg2 * 2) * 128;
    uint4 A2[2][2][2];
    #pragma unroll
    for (int mi = 0; mi < 2; mi++) {
        A2[0][mi][0] = WRp[mi * 128 + lane];             // s = 0
        A2[0][mi][1] = WRp[mi * 128 + 2 * 32 + lane];    // s = 2
    }
    #pragma unroll
    for (int s = 0; s < 2; s++) {
        int cur = s & 1, nxt = cur ^ 1;
        if (s < 1) {
            #pragma unroll
            for (int mi = 0; mi < 2; mi++) {
                A2[nxt][mi][0] = WRp[mi * 128 + 1 * 32 + lane];
                A2[nxt][mi][1] = WRp[mi * 128 + 3 * 32 + lane];
            }
        }
        uint4 B0 = Zq[(ng2 * 16 + 0 + tb) * ZQ4 + s * 4 + r];
        uint4 B1 = Zq[(ng2 * 16 + 8 + tb) * ZQ4 + s * 4 + r];
        #pragma unroll
        for (int mi = 0; mi < 2; mi++) {
            uint4 a0 = A2[cur][mi][0];
            uint4 a1 = A2[cur][mi][1];
            mma16816h(acc2[mi][0], a0.x, a0.y, a0.z, a0.w, B0.x, B0.y);
            mma16816h(acc2[mi][0], a1.x, a1.y, a1.z, a1.w, B0.z, B0.w);
            mma16816h(acc2[mi][1], a0.x, a0.y, a0.z, a0.w, B1.x, B1.y);
            mma16816h(acc2[mi][1], a1.x, a1.y, a1.z, a1.w, B1.z, B1.w);
        }
    }

    // ---- store skip ----
    {
        int gr = lane >> 2, tq = 2 * (lane & 3);
        #pragma unroll
        for (int mi = 0; mi < 2; mi++)
            #pragma unroll
            for (int j = 0; j < 2; j++) {
                int m = mg2 * 32 + mi * 16 + gr;
                int t = ng2 * 16 + j * 8 + tq;
                SK[t * 68 + m]       = acc2[mi][j][0];
                SK[(t + 1) * 68 + m] = acc2[mi][j][1];
                SK[t * 68 + m + 8]       = acc2[mi][j][2];
                SK[(t + 1) * 68 + m + 8] = acc2[mi][j][3];
            }
    }
    __syncthreads();                      // (4) SK ready

    // ---- epilogue: res_out = recon(Xq.zw, XfL) + skip + b_res ----
    uint2* oH = rowsH(out_sel, b);
    uint2* oL = rowsL(out_sel, b);
    #pragma unroll
    for (int it = 0; it < 4; it++) {
        int id = it * 256 + tid;          // 1024 = 64t x 16 slots
        int t = id >> 4, s = id & 15;
        int qc = ((s >> 2) << 3) + (s & 3);
        int c0 = 2 * qc;
        uint2 H = *(const uint2*)(smem_u + t * (XQ4 * 4) + s * 4 + 2);  // cur half
        uint2 L = XfL[t * 16 + s];
        float2 ra = recon2(H.x, L.x);
        float2 rb = recon2(H.y, L.y);
        float2 sk1 = *(const float2*)&SK[t * 68 + c0];
        float2 sk2 = *(const float2*)&SK[t * 68 + c0 + 8];
        float o0 = ra.x + sk1.x + sBR[c0];
        float o1 = ra.y + sk1.y + sBR[c0 + 1];
        float o2 = rb.x + sk2.x + sBR[c0 + 8];
        float o3 = rb.y + sk2.y + sBR[c0 + 9];
        u32 h1, l1, h2, l2;
        split2h(o0, o1, h1, l1);
        split2h(o2, o3, h2, l2);
        int gt = tt0 + t;
        oH[gt * 16 + s] = make_uint2(h1, h2);
        oL[gt * 16 + s] = make_uint2(l1, l2);
    }
}

// ---------------- K5: head (hi-only MMAs; as Round 13) ---------------------------
__global__ void __launch_bounds__(256, 2) k_final_tc(
    const float* __restrict__ b1, const float* __restrict__ b2,
    float* __restrict__ out)
{
    extern __shared__ u32 smem_u[];
    u32* XH = smem_u;                 // 64 x 36 u32
    float* Dsm = (float*)smem_u;      // overlay: 128 x 68 f32
    u32* HH = smem_u + 8704;          // 64 x 68 u32

    int tid = threadIdx.x;
    int lane = tid & 31;
    int w = tid >> 5;
    int b = blockIdx.y;
    int tt0 = blockIdx.x * 64;
    int tb = lane >> 2;

    const uint2* aH = rowsH(1, b);
    const uint2* aL = rowsL(1, b);
    const uint2* zH = rowsH(0, b);
    const uint2* zL = rowsL(0, b);
    #pragma unroll
    for (int it = 0; it < 4; it++) {
        int id = it * 256 + tid;
        int t = id >> 4, s = id & 15;
        int gt = tt0 + t;
        uint2 AH = aH[gt * 16 + s], AL = aL[gt * 16 + s];
        uint2 ZH0 = zH[gt * 16 + s], ZL0 = zL[gt * 16 + s];
        float2 a1 = recon2(AH.x, AL.x), a2 = recon2(AH.y, AL.y);
        float2 z1 = recon2(ZH0.x, ZL0.x), z2 = recon2(ZH0.y, ZL0.y);
        float s0 = fmaxf(a1.x - z1.x, 0.f), s1 = fmaxf(a1.y - z1.y, 0.f);
        float s2 = fmaxf(a2.x - z2.x, 0.f), s3 = fmaxf(a2.y - z2.y, 0.f);
        int q = ((s >> 2) << 3) + (s & 3);
        int o = t * 36 + q;
        XH[o] = pack2h(s0, s1);
        XH[o + 4] = pack2h(s2, s3);
    }
    __syncthreads();

    float acc[8][4];
    #pragma unroll
    for (int j = 0; j < 8; j++)
        #pragma unroll
        for (int rr = 0; rr < 4; rr++) acc[j][rr] = 0.f;

    const uint4* W1p = (const uint4*)(g_W1 + w * 512);
    #pragma unroll
    for (int s = 0; s < 4; s++) {
        uint4 Ah = W1p[s * 32 + lane];
        int kb = s * 8 + (lane & 3);
        #pragma unroll
        for (int j = 0; j < 8; j++) {
            int base = (j * 8 + tb) * 36 + kb;
            mma16816h(acc[j], Ah.x, Ah.y, Ah.z, Ah.w, XH[base], XH[base + 4]);
        }
    }
    __syncthreads();

    {
        int g = lane >> 2, tq = 2 * (lane & 3);
        int m = w * 16 + g;
        #pragma unroll
        for (int j = 0; j < 8; j++) {
            int t = j * 8 + tq;
            *(float2*)&Dsm[m * 68 + t] = make_float2(acc[j][0], acc[j][1]);
            *(float2*)&Dsm[(m + 8) * 68 + t] = make_float2(acc[j][2], acc[j][3]);
        }
    }
    __syncthreads();

    #pragma unroll
    for (int it = 0; it < 16; it++) {
        int id = it * 256 + tid;
        int mp = id & 63, t = id >> 6;
        float h0 = fmaxf(Dsm[(2 * mp) * 68 + t] + b1[2 * mp], 0.f);
        float h1 = fmaxf(Dsm[(2 * mp + 1) * 68 + t] + b1[2 * mp + 1], 0.f);
        HH[t * 68 + mp] = pack2h(h0, h1);
    }
    __syncthreads();

    int mt = w & 1;
    float acc2[2][4];
    #pragma unroll
    for (int j = 0; j < 2; j++)
        #pragma unroll
        for (int rr = 0; rr < 4; rr++) acc2[j][rr] = 0.f;

    const uint4* W2p = (const uint4*)(g_W2 + mt * 1024);
    #pragma unroll
    for (int s = 0; s < 8; s++) {
        uint4 Ah = W2p[s * 32 + lane];
        int kb = s * 8 + (lane & 3);
        #pragma unroll
        for (int j = 0; j < 2; j++) {
            int nblk = (w >> 1) * 2 + j;
            int base = (nblk * 8 + tb) * 68 + kb;
            mma16816h(acc2[j], Ah.x, Ah.y, Ah.z, Ah.w, HH[base], HH[base + 4]);
        }
    }

    {
        int m = mt * 16 + (lane >> 2);
        #pragma unroll
        for (int j = 0; j < 2; j++) {
            int nblk = (w >> 1) * 2 + j;
            int t = tt0 + nblk * 8 + 2 * (lane & 3);
            int o1 = m, o2 = m + 8;
            *(float2*)(out + ((size_t)b * OO + o1) * LL + t) =
                make_float2(acc2[j][0] + b2[o1], acc2[j][1] + b2[o1]);
            if (o2 < OO)
                *(float2*)(out + ((size_t)b * OO + o2) * LL + t) =
                    make_float2(acc2[j][2] + b2[o2], acc2[j][3] + b2[o2]);
        }
    }
}

// ---------------- launch ----------------------------------------------------------
extern "C" void kernel_launch(void* const* d_in, const int* in_sizes, int n_in,
                              void* d_out, int out_size)
{
    const int*   in_tok = (const int*)d_in[0];
    const int*   g_tok  = (const int*)d_in[1];
    const float* emb    = (const float*)d_in[2];
    const float* wc     = (const float*)d_in[3];
    const float* bc     = (const float*)d_in[4];
    const float* wf     = (const float*)d_in[5];
    const float* bf     = (const float*)d_in[6];
    const float* wg     = (const float*)d_in[7];
    const float* bg     = (const float*)d_in[8];
    const float* wlf    = (const float*)d_in[9];
    const float* blf    = (const float*)d_in[10];
    const float* wlg    = (const float*)d_in[11];
    const float* blg    = (const float*)d_in[12];
    const float* wres   = (const float*)d_in[13];
    const float* bres   = (const float*)d_in[14];
    const float* w1     = (const float*)d_in[15];
    const float* b1     = (const float*)d_in[16];
    const float* w2     = (const float*)d_in[17];
    const float* b2     = (const float*)d_in[18];
    float* out = (float*)d_out;

    const int LAYER_SMEM = 23488 * 4;   // 93952 B (2 blocks/SM)
    const int FINAL_SMEM = 13056 * 4;   // 52224 B
    cudaFuncSetAttribute(k_layer_tc, cudaFuncAttributeMaxDynamicSharedMemorySize, LAYER_SMEM);
    cudaFuncSetAttribute(k_final_tc, cudaFuncAttributeMaxDynamicSharedMemorySize, FINAL_SMEM);

    k_precompute_M<<<VV, 64>>>(emb, wc);
    k_prep<<<NDND + 1, 256>>>(wf, wg, wres, w1, w2);
    k_H<<<dim3(NDND, 16), 256>>>(g_tok, emb, wlf, blf, wlg, blg);
    k_init<<<dim3(LL / 64, BB), 256>>>(in_tok, bc);
    for (int i = 0; i < NDND; i++) {
        int d = 2 << i;
        int out_sel = (i % 2 == 0) ? 1 : 2;           // layer 8 -> sel 1
        int in_sel  = (i == 0) ? 0 : ((i % 2 == 0) ? 2 : 1);
        k_layer_tc<<<dim3(LL / 64, BB), 256, LAYER_SMEM>>>(
            bf, bg, bres, i, d, in_sel, out_sel);
    }
    k_final_tc<<<dim3(LL / 64, BB), 256, FINAL_SMEM>>>(b1, b2, out);
}

// round 15
// speedup vs baseline: 1.5634x; 1.1486x over previous
#include <cuda_runtime.h>
#include <cuda_fp16.h>
#include <math.h>

#define BB   64
#define LL   2048
#define VV   30
#define EE   128
#define GG   8
#define GEGE 1024
#define CC   64
#define FF   128
#define OO   30
#define NDND 9

#define XQ4  20    // uint4 pitch per t-row, X packed slots
#define ZP32 36    // u32 pitch per t-row of z halves (64 ch = 32 u32 + 4 pad)
#define RSCALE 2048.0f
#define RSCALE_INV 4.8828125e-4f

typedef unsigned int u32;
typedef unsigned short u16;

// ---------------- helpers ----------------------------------------------------
__device__ __forceinline__ void mma16816h(float* d, u32 a0, u32 a1, u32 a2, u32 a3,
                                          u32 b0, u32 b1) {
    asm volatile(
        "mma.sync.aligned.m16n8k16.row.col.f32.f16.f16.f32 "
        "{%0,%1,%2,%3}, {%4,%5,%6,%7}, {%8,%9}, {%0,%1,%2,%3};"
        : "+f"(d[0]), "+f"(d[1]), "+f"(d[2]), "+f"(d[3])
        : "r"(a0), "r"(a1), "r"(a2), "r"(a3), "r"(b0), "r"(b1));
}
__device__ __forceinline__ void split2h(float x0, float x1, u32& hi, u32& lo) {
    __half h0 = __float2half_rn(x0);
    __half h1 = __float2half_rn(x1);
    float r0 = (x0 - __half2float(h0)) * RSCALE;
    float r1 = (x1 - __half2float(h1)) * RSCALE;
    __half2 hv = __halves2half2(h0, h1);
    __half2 lv = __halves2half2(__float2half_rn(r0), __float2half_rn(r1));
    hi = *(u32*)&hv; lo = *(u32*)&lv;
}
__device__ __forceinline__ u32 pack2h(float x0, float x1) {
    __half2 hv = __halves2half2(__float2half_rn(x0), __float2half_rn(x1));
    return *(u32*)&hv;
}
__device__ __forceinline__ float2 recon2(u32 h, u32 l) {
    float2 a = __half22float2(*(__half2*)&h);
    float2 b = __half22float2(*(__half2*)&l);
    return make_float2(fmaf(b.x, RSCALE_INV, a.x), fmaf(b.y, RSCALE_INV, a.y));
}
__device__ __forceinline__ float fast_tanh(float x) {
    float e; asm("ex2.approx.f32 %0, %1;" : "=f"(e) : "f"(x * 2.8853900817779268f));
    float r; asm("rcp.approx.f32 %0, %1;" : "=f"(r) : "f"(e + 1.0f));
    return 1.0f - 2.0f * r;
}
__device__ __forceinline__ float fast_sigmoid(float x) {
    float e; asm("ex2.approx.f32 %0, %1;" : "=f"(e) : "f"(-x * 1.4426950408889634f));
    float r; asm("rcp.approx.f32 %0, %1;" : "=f"(r) : "f"(e + 1.0f));
    return r;
}

// ---------------- scratch -----------------------------------------------------
__device__ uint2 g_rH[(size_t)3 * BB * LL * 16];
__device__ uint2 g_rL[(size_t)3 * BB * LL * 16];
__device__ float g_HF[NDND * BB * CC];
__device__ float g_HG[NDND * BB * CC];
__device__ float g_M0[VV * CC];
__device__ float g_M1[VV * CC];
__device__ u32 g_WF[NDND * 8192];
__device__ u32 g_WR[NDND * 2048];
__device__ u32 g_W1[4096];
__device__ u32 g_W2[2048];

__device__ __forceinline__ uint2* rowsH(int sel, int b) {
    return g_rH + ((size_t)sel * BB + b) * LL * 16;
}
__device__ __forceinline__ uint2* rowsL(int sel, int b) {
    return g_rL + ((size_t)sel * BB + b) * LL * 16;
}

// ---------------- K0a: fold embedding + initial conv ---------------------------
__global__ void __launch_bounds__(64) k_precompute_M(
    const float* __restrict__ emb, const float* __restrict__ wc)
{
    int v = blockIdx.x, c = threadIdx.x;
    float a0 = 0.f, a1 = 0.f;
    if (v != 0) {
        for (int e = 0; e < EE; e++) {
            float x = emb[v * EE + e];
            a0 = fmaf(x, wc[(c * EE + e) * 2 + 0], a0);
            a1 = fmaf(x, wc[(c * EE + e) * 2 + 1], a1);
        }
    }
    g_M0[v * CC + c] = a0;
    g_M1[v * CC + c] = a1;
}

// ---------------- K0b: all weights -> fp16 fragment layout ----------------------
__global__ void __launch_bounds__(256) k_prep(
    const float* __restrict__ wf, const float* __restrict__ wg,
    const float* __restrict__ wres,
    const float* __restrict__ w1, const float* __restrict__ w2)
{
    int layer = blockIdx.x;
    if (layer < NDND) {
        for (int idx = threadIdx.x; idx < 8192; idx += 256) {
            int w = idx >> 10, s = (idx >> 7) & 7;
            int lane = (idx >> 2) & 31, r = idx & 3;
            int m = w * 16 + (r & 1) * 8 + (lane >> 2);
            int k0 = s * 16 + ((r >> 1) & 1) * 8 + (lane & 3) * 2;
            const float* src = (m < 64) ? wf : wg;
            int cout = m & 63;
            int cin0 = k0 & 63, tap0 = k0 >> 6;
            int k1 = k0 + 1;
            int cin1 = k1 & 63, tap1 = k1 >> 6;
            float x0 = src[(((size_t)layer * 64 + cout) * 64 + cin0) * 2 + tap0];
            float x1 = src[(((size_t)layer * 64 + cout) * 64 + cin1) * 2 + tap1];
            g_WF[(size_t)layer * 8192 + idx] = pack2h(x0, x1);
        }
        for (int idx = threadIdx.x; idx < 2048; idx += 256) {
            int mt = idx >> 9, s = (idx >> 7) & 3;
            int lane = (idx >> 2) & 31, r = idx & 3;
            int m = mt * 16 + (r & 1) * 8 + (lane >> 2);
            int k0 = s * 16 + ((r >> 1) & 1) * 8 + (lane & 3) * 2;
            float x0 = wres[((size_t)layer * 64 + m) * 64 + k0];
            float x1 = wres[((size_t)layer * 64 + m) * 64 + k0 + 1];
            g_WR[(size_t)layer * 2048 + idx] = pack2h(x0, x1);
        }
    } else {
        for (int idx = threadIdx.x; idx < 4096; idx += 256) {
            int w = idx >> 9, s = (idx >> 7) & 3;
            int lane = (idx >> 2) & 31, r = idx & 3;
            int m = w * 16 + (r & 1) * 8 + (lane >> 2);
            int k0 = s * 16 + ((r >> 1) & 1) * 8 + (lane & 3) * 2;
            g_W1[idx] = pack2h(w1[m * 64 + k0], w1[m * 64 + k0 + 1]);
        }
        for (int idx = threadIdx.x; idx < 2048; idx += 256) {
            int mt = idx >> 10, s = (idx >> 7) & 7;
            int lane = (idx >> 2) & 31, r = idx & 3;
            int m = mt * 16 + (r & 1) * 8 + (lane >> 2);
            int k0 = s * 16 + ((r >> 1) & 1) * 8 + (lane & 3) * 2;
            float x0 = (m < OO) ? w2[m * 128 + k0] : 0.f;
            float x1 = (m < OO) ? w2[m * 128 + k0 + 1] : 0.f;
            g_W2[idx] = pack2h(x0, x1);
        }
    }
}

// ---------------- K2: conditioning vectors (embedding gather fused) -------------
__global__ void __launch_bounds__(256) k_H(
    const int* __restrict__ gin, const float* __restrict__ emb,
    const float* __restrict__ wlf, const float* __restrict__ blf,
    const float* __restrict__ wlg, const float* __restrict__ blg)
{
    __shared__ float sE[GEGE * 4];
    __shared__ float sR[256 * 4];
    int i = blockIdx.x;
    int b0 = blockIdx.y * 4;
    int tid = threadIdx.x;

    for (int idx = tid; idx < GEGE * 4; idx += 256) {
        int k = idx >> 2, bj = idx & 3;
        int g = k >> 7, e = k & 127;
        int tok = gin[(b0 + bj) * GG + g];
        sE[idx] = (tok == 0) ? 0.f : emb[tok * EE + e];
    }
    __syncthreads();

    int row = tid & 127;
    int half = tid >> 7;
    int c = row & 63;
    bool isf = row < 64;
    const float* w = (isf ? wlf : wlg) + ((size_t)i * CC + c) * GEGE + half * 512;
    const float* ep = sE + half * 512 * 4;

    float a0 = 0.f, a1 = 0.f, a2 = 0.f, a3 = 0.f;
    #pragma unroll 4
    for (int k = 0; k < 512; k += 4) {
        float4 wv = *(const float4*)(w + k);
        float4 e0 = *(const float4*)(ep + k * 4);
        float4 e1 = *(const float4*)(ep + k * 4 + 4);
        float4 e2 = *(const float4*)(ep + k * 4 + 8);
        float4 e3 = *(const float4*)(ep + k * 4 + 12);
        a0 = fmaf(wv.x, e0.x, a0); a1 = fmaf(wv.x, e0.y, a1);
        a2 = fmaf(wv.x, e0.z, a2); a3 = fmaf(wv.x, e0.w, a3);
        a0 = fmaf(wv.y, e1.x, a0); a1 = fmaf(wv.y, e1.y, a1);
        a2 = fmaf(wv.y, e1.z, a2); a3 = fmaf(wv.y, e1.w, a3);
        a0 = fmaf(wv.z, e2.x, a0); a1 = fmaf(wv.z, e2.y, a1);
        a2 = fmaf(wv.z, e2.z, a2); a3 = fmaf(wv.z, e2.w, a3);
        a0 = fmaf(wv.w, e3.x, a0); a1 = fmaf(wv.w, e3.y, a1);
        a2 = fmaf(wv.w, e3.z, a2); a3 = fmaf(wv.w, e3.w, a3);
    }
    *(float4*)&sR[tid * 4] = make_float4(a0, a1, a2, a3);
    __syncthreads();
    if (tid < 128) {
        float4 lo = *(const float4*)&sR[tid * 4];
        float4 hi = *(const float4*)&sR[(tid + 128) * 4];
        float bias = (isf ? blf : blg)[i * CC + c];
        float* dst = (isf ? g_HF : g_HG);
        dst[((size_t)i * BB + b0 + 0) * CC + c] = lo.x + hi.x + bias;
        dst[((size_t)i * BB + b0 + 1) * CC + c] = lo.y + hi.y + bias;
        dst[((size_t)i * BB + b0 + 2) * CC + c] = lo.z + hi.z + bias;
        dst[((size_t)i * BB + b0 + 3) * CC + c] = lo.w + hi.w + bias;
    }
}

// ---------------- K3: initial residual -> split slot format ----------------------
__global__ void __launch_bounds__(256) k_init(
    const int* __restrict__ tok, const float* __restrict__ b_causal)
{
    __shared__ float sM0[VV * CC], sM1[VV * CC], sb[CC];
    int tid = threadIdx.x;
    for (int i = tid; i < VV * CC; i += 256) { sM0[i] = g_M0[i]; sM1[i] = g_M1[i]; }
    if (tid < CC) sb[tid] = b_causal[tid];
    __syncthreads();
    int b = blockIdx.y, tt0 = blockIdx.x * 64;
    const int* tb = tok + b * LL;
    uint2* oH = rowsH(0, b);
    uint2* oL = rowsL(0, b);
    for (int idx = tid; idx < 1024; idx += 256) {
        int tl = idx >> 4, s = idx & 15;
        int qc = ((s >> 2) << 3) + (s & 3);
        int c0 = 2 * qc;
        int t = tt0 + tl;
        int v1 = tb[t] * CC;
        float r[4];
        r[0] = sM1[v1 + c0] + sb[c0];
        r[1] = sM1[v1 + c0 + 1] + sb[c0 + 1];
        r[2] = sM1[v1 + c0 + 8] + sb[c0 + 8];
        r[3] = sM1[v1 + c0 + 9] + sb[c0 + 9];
        if (t > 0) {
            int v0 = tb[t - 1] * CC;
            r[0] += sM0[v0 + c0];
            r[1] += sM0[v0 + c0 + 1];
            r[2] += sM0[v0 + c0 + 8];
            r[3] += sM0[v0 + c0 + 9];
        }
        u32 h1, l1, h2, l2;
        split2h(r[0], r[1], h1, l1);
        split2h(r[2], r[3], h2, l2);
        oH[t * 16 + s] = make_uint2(h1, h2);
        oL[t * 16 + s] = make_uint2(l1, l2);
    }
}

// ---------------- K4: dilated residual layer (reg-resident activation) ----------
// Warp mg computes f rows [mg*16,+16) AND g rows [64+mg*16,+16) -> activation in
// registers; z stored once as fp16 halves [t][c] (pitch ZP32 u32); GEMM2 B reads
// u32 kpairs directly from sZ.
// SMEM (u32): Xq@0 (5120) | XfL@5120 (2048) | sZ@7168 (2304) | SK@9472 (4352)
//             biases@13824 (192) = 56064 B
__global__ void __launch_bounds__(256, 2) k_layer_tc(
    const float* __restrict__ b_f, const float* __restrict__ b_g,
    const float* __restrict__ b_res,
    int layer, int d, int in_sel, int out_sel)
{
    extern __shared__ u32 smem_u[];
    uint4* Xq  = (uint4*)smem_u;                   // 64 x XQ4
    uint2* XfL = (uint2*)(smem_u + 5120);          // [t][j] pitch 16 (cur lo)
    u32*   sZ  = smem_u + 7168;                    // [t][cpair] pitch ZP32
    float* SK  = (float*)(smem_u + 9472);          // 64 x 68
    float* sBF = (float*)(smem_u + 13824);         // 64
    float* sBG = sBF + 64;
    float* sBR = sBG + 64;

    int tid = threadIdx.x;
    int lane = tid & 31;
    int w = tid >> 5;
    int b = blockIdx.y;
    int tt0 = blockIdx.x * 64;
    int r = lane & 3, tb = lane >> 2;

    if (tid < 64)
        sBF[tid] = b_f[layer * CC + tid] + g_HF[((size_t)layer * BB + b) * CC + tid];
    else if (tid < 128) {
        int c = tid - 64;
        sBG[c] = b_g[layer * CC + c] + g_HG[((size_t)layer * BB + b) * CC + c];
    } else if (tid < 192) {
        int c = tid - 128;
        sBR[c] = b_res[layer * CC + c];
    }

    // ---- build Xq: prev-hi in .xy, cur-hi in .zw; cur-lo in XfL ----
    const uint2* iH = rowsH(in_sel, b);
    const uint2* iL = rowsL(in_sel, b);
    #pragma unroll
    for (int it = 0; it < 4; it++) {
        int id = it * 256 + tid;          // 1024 = 64t x 16 j
        int t = id >> 4, j = id & 15;
        int gtp = tt0 + t - d;
        int gtc = tt0 + t;
        uint2 P = make_uint2(0u, 0u);
        if (gtp >= 0) P = iH[gtp * 16 + j];
        uint2 C = iH[gtc * 16 + j];
        Xq[t * XQ4 + j] = make_uint4(P.x, P.y, C.x, C.y);
        XfL[t * 16 + j] = iL[gtc * 16 + j];
    }
    __syncthreads();                      // (1) X ready

    // ---- GEMM1: warp mg does f-tile mg and g-tile 4+mg (same channels) ----
    int mg = w & 3, ng = w >> 2;
    float acc[2][4][4];                   // [0]=f, [1]=g
    #pragma unroll
    for (int mi = 0; mi < 2; mi++)
        #pragma unroll
        for (int j = 0; j < 4; j++)
            #pragma unroll
            for (int rr = 0; rr < 4; rr++) acc[mi][j][rr] = 0.f;

    const uint4* WFb = (const uint4*)(g_WF + (size_t)layer * 8192);
    const uint4* WFf = WFb + mg * 256;         // f tile
    const uint4* WFg = WFb + (4 + mg) * 256;   // g tile
    uint4 A[2][2][2];   // [buf][mi][half]
    A[0][0][0] = WFf[lane];           A[0][0][1] = WFf[4 * 32 + lane];
    A[0][1][0] = WFg[lane];           A[0][1][1] = WFg[4 * 32 + lane];
    #pragma unroll
    for (int s = 0; s < 4; s++) {
        int cur = s & 1, nxt = cur ^ 1;
        if (s < 3) {
            A[nxt][0][0] = WFf[(s + 1) * 32 + lane];
            A[nxt][0][1] = WFf[(s + 5) * 32 + lane];
            A[nxt][1][0] = WFg[(s + 1) * 32 + lane];
            A[nxt][1][1] = WFg[(s + 5) * 32 + lane];
        }
        uint4 B0 = Xq[(ng * 32 + 0 + tb) * XQ4 + s * 4 + r];
        uint4 B1 = Xq[(ng * 32 + 8 + tb) * XQ4 + s * 4 + r];
        uint4 B2 = Xq[(ng * 32 + 16 + tb) * XQ4 + s * 4 + r];
        uint4 B3 = Xq[(ng * 32 + 24 + tb) * XQ4 + s * 4 + r];
        #pragma unroll
        for (int mi = 0; mi < 2; mi++) {
            uint4 a0 = A[cur][mi][0];
            uint4 a1 = A[cur][mi][1];
            mma16816h(acc[mi][0], a0.x, a0.y, a0.z, a0.w, B0.x, B0.y);
            mma16816h(acc[mi][0], a1.x, a1.y, a1.z, a1.w, B0.z, B0.w);
            mma16816h(acc[mi][1], a0.x, a0.y, a0.z, a0.w, B1.x, B1.y);
            mma16816h(acc[mi][1], a1.x, a1.y, a1.z, a1.w, B1.z, B1.w);
            mma16816h(acc[mi][2], a0.x, a0.y, a0.z, a0.w, B2.x, B2.y);
            mma16816h(acc[mi][2], a1.x, a1.y, a1.z, a1.w, B2.z, B2.w);
            mma16816h(acc[mi][3], a0.x, a0.y, a0.z, a0.w, B3.x, B3.y);
            mma16816h(acc[mi][3], a1.x, a1.y, a1.z, a1.w, B3.z, B3.w);
        }
    }

    // ---- register-resident gated activation -> z halves into sZ[t][c] ----
    {
        int gr = lane >> 2, tq = 2 * (lane & 3);
        int c1 = mg * 16 + gr;
        int c2 = c1 + 8;
        float bf1 = sBF[c1], bf2 = sBF[c2];
        float bg1 = sBG[c1], bg2 = sBG[c2];
        u16* sZh = (u16*)sZ;
        #pragma unroll
        for (int j = 0; j < 4; j++) {
            int t0 = ng * 32 + j * 8 + tq;
            #pragma unroll
            for (int rr = 0; rr < 4; rr++) {
                int c = (rr < 2) ? c1 : c2;
                float bf = (rr < 2) ? bf1 : bf2;
                float bg = (rr < 2) ? bg1 : bg2;
                int t = t0 + (rr & 1);
                float z = fast_tanh(acc[0][j][rr] + bf) *
                          fast_sigmoid(acc[1][j][rr] + bg);
                __half zh = __float2half_rn(z);
                sZh[t * (ZP32 * 2) + c] = *(u16*)&zh;
            }
        }
    }
    __syncthreads();                      // (2) z ready

    // ---- GEMM2: B kpairs read directly from sZ ----
    int mg2 = w & 1, ng2 = w >> 1;
    float acc2[2][2][4];
    #pragma unroll
    for (int mi = 0; mi < 2; mi++)
        #pragma unroll
        for (int j = 0; j < 2; j++)
            #pragma unroll
            for (int rr = 0; rr < 4; rr++) acc2[mi][j][rr] = 0.f;

    const uint4* WRp = (const uint4*)(g_WR + (size_t)layer * 2048) + (mg2 * 2) * 128;
    uint4 A2[2][2];
    #pragma unroll
    for (int mi = 0; mi < 2; mi++) A2[0][mi] = WRp[mi * 128 + lane];
    #pragma unroll
    for (int s = 0; s < 4; s++) {
        int cur = s & 1, nxt = cur ^ 1;
        if (s < 3) {
            #pragma unroll
            for (int mi = 0; mi < 2; mi++)
                A2[nxt][mi] = WRp[mi * 128 + (s + 1) * 32 + lane];
        }
        int q = s * 8 + r;                // kpair index (u32 within t-row)
        int ta = ng2 * 16 + tb;
        u32 b00 = sZ[ta * ZP32 + q];
        u32 b01 = sZ[ta * ZP32 + q + 4];
        u32 b10 = sZ[(ta + 8) * ZP32 + q];
        u32 b11 = sZ[(ta + 8) * ZP32 + q + 4];
        #pragma unroll
        for (int mi = 0; mi < 2; mi++) {
            uint4 Ah = A2[cur][mi];
            mma16816h(acc2[mi][0], Ah.x, Ah.y, Ah.z, Ah.w, b00, b01);
            mma16816h(acc2[mi][1], Ah.x, Ah.y, Ah.z, Ah.w, b10, b11);
        }
    }

    // ---- store skip ----
    {
        int gr = lane >> 2, tq = 2 * (lane & 3);
        #pragma unroll
        for (int mi = 0; mi < 2; mi++)
            #pragma unroll
            for (int j = 0; j < 2; j++) {
                int m = mg2 * 32 + mi * 16 + gr;
                int t = ng2 * 16 + j * 8 + tq;
                SK[t * 68 + m]       = acc2[mi][j][0];
                SK[(t + 1) * 68 + m] = acc2[mi][j][1];
                SK[t * 68 + m + 8]       = acc2[mi][j][2];
                SK[(t + 1) * 68 + m + 8] = acc2[mi][j][3];
            }
    }
    __syncthreads();                      // (3) SK ready

    // ---- epilogue: res_out = recon(Xq.zw, XfL) + skip + b_res ----
    uint2* oH = rowsH(out_sel, b);
    uint2* oL = rowsL(out_sel, b);
    #pragma unroll
    for (int it = 0; it < 4; it++) {
        int id = it * 256 + tid;          // 1024 = 64t x 16 slots
        int t = id >> 4, s = id & 15;
        int qc = ((s >> 2) << 3) + (s & 3);
        int c0 = 2 * qc;
        uint2 H = *(const uint2*)(smem_u + t * (XQ4 * 4) + s * 4 + 2);
        uint2 L = XfL[t * 16 + s];
        float2 ra = recon2(H.x, L.x);
        float2 rb = recon2(H.y, L.y);
        float2 sk1 = *(const float2*)&SK[t * 68 + c0];
        float2 sk2 = *(const float2*)&SK[t * 68 + c0 + 8];
        float o0 = ra.x + sk1.x + sBR[c0];
        float o1 = ra.y + sk1.y + sBR[c0 + 1];
        float o2 = rb.x + sk2.x + sBR[c0 + 8];
        float o3 = rb.y + sk2.y + sBR[c0 + 9];
        u32 h1, l1, h2, l2;
        split2h(o0, o1, h1, l1);
        split2h(o2, o3, h2, l2);
        int gt = tt0 + t;
        oH[gt * 16 + s] = make_uint2(h1, h2);
        oL[gt * 16 + s] = make_uint2(l1, l2);
    }
}

// ---------------- K5: head (hi-only MMAs; as Round 14) ---------------------------
__global__ void __launch_bounds__(256, 2) k_final_tc(
    const float* __restrict__ b1, const float* __restrict__ b2,
    float* __restrict__ out)
{
    extern __shared__ u32 smem_u[];
    u32* XH = smem_u;                 // 64 x 36 u32
    float* Dsm = (float*)smem_u;      // overlay: 128 x 68 f32
    u32* HH = smem_u + 8704;          // 64 x 68 u32

    int tid = threadIdx.x;
    int lane = tid & 31;
    int w = tid >> 5;
    int b = blockIdx.y;
    int tt0 = blockIdx.x * 64;
    int tb = lane >> 2;

    const uint2* aH = rowsH(1, b);
    const uint2* aL = rowsL(1, b);
    const uint2* zH = rowsH(0, b);
    const uint2* zL = rowsL(0, b);
    #pragma unroll
    for (int it = 0; it < 4; it++) {
        int id = it * 256 + tid;
        int t = id >> 4, s = id & 15;
        int gt = tt0 + t;
        uint2 AH = aH[gt * 16 + s], AL = aL[gt * 16 + s];
        uint2 ZH0 = zH[gt * 16 + s], ZL0 = zL[gt * 16 + s];
        float2 a1 = recon2(AH.x, AL.x), a2 = recon2(AH.y, AL.y);
        float2 z1 = recon2(ZH0.x, ZL0.x), z2 = recon2(ZH0.y, ZL0.y);
        float s0 = fmaxf(a1.x - z1.x, 0.f), s1 = fmaxf(a1.y - z1.y, 0.f);
        float s2 = fmaxf(a2.x - z2.x, 0.f), s3 = fmaxf(a2.y - z2.y, 0.f);
        int q = ((s >> 2) << 3) + (s & 3);
        int o = t * 36 + q;
        XH[o] = pack2h(s0, s1);
        XH[o + 4] = pack2h(s2, s3);
    }
    __syncthreads();

    float acc[8][4];
    #pragma unroll
    for (int j = 0; j < 8; j++)
        #pragma unroll
        for (int rr = 0; rr < 4; rr++) acc[j][rr] = 0.f;

    const uint4* W1p = (const uint4*)(g_W1 + w * 512);
    #pragma unroll
    for (int s = 0; s < 4; s++) {
        uint4 Ah = W1p[s * 32 + lane];
        int kb = s * 8 + (lane & 3);
        #pragma unroll
        for (int j = 0; j < 8; j++) {
            int base = (j * 8 + tb) * 36 + kb;
            mma16816h(acc[j], Ah.x, Ah.y, Ah.z, Ah.w, XH[base], XH[base + 4]);
        }
    }
    __syncthreads();

    {
        int g = lane >> 2, tq = 2 * (lane & 3);
        int m = w * 16 + g;
        #pragma unroll
        for (int j = 0; j < 8; j++) {
            int t = j * 8 + tq;
            *(float2*)&Dsm[m * 68 + t] = make_float2(acc[j][0], acc[j][1]);
            *(float2*)&Dsm[(m + 8) * 68 + t] = make_float2(acc[j][2], acc[j][3]);
        }
    }
    __syncthreads();

    #pragma unroll
    for (int it = 0; it < 16; it++) {
        int id = it * 256 + tid;
        int mp = id & 63, t = id >> 6;
        float h0 = fmaxf(Dsm[(2 * mp) * 68 + t] + b1[2 * mp], 0.f);
        float h1 = fmaxf(Dsm[(2 * mp + 1) * 68 + t] + b1[2 * mp + 1], 0.f);
        HH[t * 68 + mp] = pack2h(h0, h1);
    }
    __syncthreads();

    int mt = w & 1;
    float acc2[2][4];
    #pragma unroll
    for (int j = 0; j < 2; j++)
        #pragma unroll
        for (int rr = 0; rr < 4; rr++) acc2[j][rr] = 0.f;

    const uint4* W2p = (const uint4*)(g_W2 + mt * 1024);
    #pragma unroll
    for (int s = 0; s < 8; s++) {
        uint4 Ah = W2p[s * 32 + lane];
        int kb = s * 8 + (lane & 3);
        #pragma unroll
        for (int j = 0; j < 2; j++) {
            int nblk = (w >> 1) * 2 + j;
            int base = (nblk * 8 + tb) * 68 + kb;
            mma16816h(acc2[j], Ah.x, Ah.y, Ah.z, Ah.w, HH[base], HH[base + 4]);
        }
    }

    {
        int m = mt * 16 + (lane >> 2);
        #pragma unroll
        for (int j = 0; j < 2; j++) {
            int nblk = (w >> 1) * 2 + j;
            int t = tt0 + nblk * 8 + 2 * (lane & 3);
            int o1 = m, o2 = m + 8;
            *(float2*)(out + ((size_t)b * OO + o1) * LL + t) =
                make_float2(acc2[j][0] + b2[o1], acc2[j][1] + b2[o1]);
            if (o2 < OO)
                *(float2*)(out + ((size_t)b * OO + o2) * LL + t) =
                    make_float2(acc2[j][2] + b2[o2], acc2[j][3] + b2[o2]);
        }
    }
}

// ---------------- launch ----------------------------------------------------------
extern "C" void kernel_launch(void* const* d_in, const int* in_sizes, int n_in,
                              void* d_out, int out_size)
{
    const int*   in_tok = (const int*)d_in[0];
    const int*   g_tok  = (const int*)d_in[1];
    const float* emb    = (const float*)d_in[2];
    const float* wc     = (const float*)d_in[3];
    const float* bc     = (const float*)d_in[4];
    const float* wf     = (const float*)d_in[5];
    const float* bf     = (const float*)d_in[6];
    const float* wg     = (const float*)d_in[7];
    const float* bg     = (const float*)d_in[8];
    const float* wlf    = (const float*)d_in[9];
    const float* blf    = (const float*)d_in[10];
    const float* wlg    = (const float*)d_in[11];
    const float* blg    = (const float*)d_in[12];
    const float* wres   = (const float*)d_in[13];
    const float* bres   = (const float*)d_in[14];
    const float* w1     = (const float*)d_in[15];
    const float* b1     = (const float*)d_in[16];
    const float* w2     = (const float*)d_in[17];
    const float* b2     = (const float*)d_in[18];
    float* out = (float*)d_out;

    const int LAYER_SMEM = 14016 * 4;   // 56064 B (2 blocks/SM)
    const int FINAL_SMEM = 13056 * 4;   // 52224 B
    cudaFuncSetAttribute(k_layer_tc, cudaFuncAttributeMaxDynamicSharedMemorySize, LAYER_SMEM);
    cudaFuncSetAttribute(k_final_tc, cudaFuncAttributeMaxDynamicSharedMemorySize, FINAL_SMEM);

    k_precompute_M<<<VV, 64>>>(emb, wc);
    k_prep<<<NDND + 1, 256>>>(wf, wg, wres, w1, w2);
    k_H<<<dim3(NDND, 16), 256>>>(g_tok, emb, wlf, blf, wlg, blg);
    k_init<<<dim3(LL / 64, BB), 256>>>(in_tok, bc);
    for (int i = 0; i < NDND; i++) {
        int d = 2 << i;
        int out_sel = (i % 2 == 0) ? 1 : 2;           // layer 8 -> sel 1
        int in_sel  = (i == 0) ? 0 : ((i % 2 == 0) ? 2 : 1);
        k_layer_tc<<<dim3(LL / 64, BB), 256, LAYER_SMEM>>>(
            bf, bg, bres, i, d, in_sel, out_sel);
    }
    k_final_tc<<<dim3(LL / 64, BB), 256, FINAL_SMEM>>>(b1, b2, out);
}

// round 16
// speedup vs baseline: 1.6518x; 1.0565x over previous
#include <cuda_runtime.h>
#include <cuda_fp16.h>
#include <math.h>

#define BB   64
#define LL   2048
#define VV   30
#define EE   128
#define GG   8
#define GEGE 1024
#define CC   64
#define FF   128
#define OO   30
#define NDND 9

#define XQ4  20    // uint4 pitch per t-row, X packed slots
#define ZP32 36    // u32 pitch per t-row of z halves
#define RSCALE 2048.0f
#define RSCALE_INV 4.8828125e-4f

typedef unsigned int u32;
typedef unsigned short u16;

// ---------------- helpers ----------------------------------------------------
__device__ __forceinline__ void mma16816h(float* d, u32 a0, u32 a1, u32 a2, u32 a3,
                                          u32 b0, u32 b1) {
    asm volatile(
        "mma.sync.aligned.m16n8k16.row.col.f32.f16.f16.f32 "
        "{%0,%1,%2,%3}, {%4,%5,%6,%7}, {%8,%9}, {%0,%1,%2,%3};"
        : "+f"(d[0]), "+f"(d[1]), "+f"(d[2]), "+f"(d[3])
        : "r"(a0), "r"(a1), "r"(a2), "r"(a3), "r"(b0), "r"(b1));
}
__device__ __forceinline__ void split2h(float x0, float x1, u32& hi, u32& lo) {
    __half h0 = __float2half_rn(x0);
    __half h1 = __float2half_rn(x1);
    float r0 = (x0 - __half2float(h0)) * RSCALE;
    float r1 = (x1 - __half2float(h1)) * RSCALE;
    __half2 hv = __halves2half2(h0, h1);
    __half2 lv = __halves2half2(__float2half_rn(r0), __float2half_rn(r1));
    hi = *(u32*)&hv; lo = *(u32*)&lv;
}
__device__ __forceinline__ u32 pack2h(float x0, float x1) {
    __half2 hv = __halves2half2(__float2half_rn(x0), __float2half_rn(x1));
    return *(u32*)&hv;
}
__device__ __forceinline__ float2 recon2(u32 h, u32 l) {
    float2 a = __half22float2(*(__half2*)&h);
    float2 b = __half22float2(*(__half2*)&l);
    return make_float2(fmaf(b.x, RSCALE_INV, a.x), fmaf(b.y, RSCALE_INV, a.y));
}
__device__ __forceinline__ float fast_tanh(float x) {
    float e; asm("ex2.approx.f32 %0, %1;" : "=f"(e) : "f"(x * 2.8853900817779268f));
    float r; asm("rcp.approx.f32 %0, %1;" : "=f"(r) : "f"(e + 1.0f));
    return 1.0f - 2.0f * r;
}
__device__ __forceinline__ float fast_sigmoid(float x) {
    float e; asm("ex2.approx.f32 %0, %1;" : "=f"(e) : "f"(-x * 1.4426950408889634f));
    float r; asm("rcp.approx.f32 %0, %1;" : "=f"(r) : "f"(e + 1.0f));
    return r;
}

// ---------------- scratch -----------------------------------------------------
__device__ uint2 g_rH[(size_t)3 * BB * LL * 16];
__device__ uint2 g_rL[(size_t)3 * BB * LL * 16];
__device__ float g_HF[NDND * BB * CC];
__device__ float g_HG[NDND * BB * CC];
__device__ float g_M0[VV * CC];
__device__ float g_M1[VV * CC];
__device__ u32 g_WF[NDND * 8192];
__device__ u32 g_WR[NDND * 2048];
__device__ u32 g_W1[4096];
__device__ u32 g_W2[2048];

__device__ __forceinline__ uint2* rowsH(int sel, int b) {
    return g_rH + ((size_t)sel * BB + b) * LL * 16;
}
__device__ __forceinline__ uint2* rowsL(int sel, int b) {
    return g_rL + ((size_t)sel * BB + b) * LL * 16;
}

// ---------------- K0a: fold embedding + initial conv ---------------------------
__global__ void __launch_bounds__(64) k_precompute_M(
    const float* __restrict__ emb, const float* __restrict__ wc)
{
    int v = blockIdx.x, c = threadIdx.x;
    float a0 = 0.f, a1 = 0.f;
    if (v != 0) {
        for (int e = 0; e < EE; e++) {
            float x = emb[v * EE + e];
            a0 = fmaf(x, wc[(c * EE + e) * 2 + 0], a0);
            a1 = fmaf(x, wc[(c * EE + e) * 2 + 1], a1);
        }
    }
    g_M0[v * CC + c] = a0;
    g_M1[v * CC + c] = a1;
}

// ---------------- K0b: all weights -> fp16 fragment layout ----------------------
__global__ void __launch_bounds__(256) k_prep(
    const float* __restrict__ wf, const float* __restrict__ wg,
    const float* __restrict__ wres,
    const float* __restrict__ w1, const float* __restrict__ w2)
{
    int layer = blockIdx.x;
    if (layer < NDND) {
        for (int idx = threadIdx.x; idx < 8192; idx += 256) {
            int w = idx >> 10, s = (idx >> 7) & 7;
            int lane = (idx >> 2) & 31, r = idx & 3;
            int m = w * 16 + (r & 1) * 8 + (lane >> 2);
            int k0 = s * 16 + ((r >> 1) & 1) * 8 + (lane & 3) * 2;
            const float* src = (m < 64) ? wf : wg;
            int cout = m & 63;
            int cin0 = k0 & 63, tap0 = k0 >> 6;
            int k1 = k0 + 1;
            int cin1 = k1 & 63, tap1 = k1 >> 6;
            float x0 = src[(((size_t)layer * 64 + cout) * 64 + cin0) * 2 + tap0];
            float x1 = src[(((size_t)layer * 64 + cout) * 64 + cin1) * 2 + tap1];
            g_WF[(size_t)layer * 8192 + idx] = pack2h(x0, x1);
        }
        for (int idx = threadIdx.x; idx < 2048; idx += 256) {
            int mt = idx >> 9, s = (idx >> 7) & 3;
            int lane = (idx >> 2) & 31, r = idx & 3;
            int m = mt * 16 + (r & 1) * 8 + (lane >> 2);
            int k0 = s * 16 + ((r >> 1) & 1) * 8 + (lane & 3) * 2;
            float x0 = wres[((size_t)layer * 64 + m) * 64 + k0];
            float x1 = wres[((size_t)layer * 64 + m) * 64 + k0 + 1];
            g_WR[(size_t)layer * 2048 + idx] = pack2h(x0, x1);
        }
    } else {
        for (int idx = threadIdx.x; idx < 4096; idx += 256) {
            int w = idx >> 9, s = (idx >> 7) & 3;
            int lane = (idx >> 2) & 31, r = idx & 3;
            int m = w * 16 + (r & 1) * 8 + (lane >> 2);
            int k0 = s * 16 + ((r >> 1) & 1) * 8 + (lane & 3) * 2;
            g_W1[idx] = pack2h(w1[m * 64 + k0], w1[m * 64 + k0 + 1]);
        }
        for (int idx = threadIdx.x; idx < 2048; idx += 256) {
            int mt = idx >> 10, s = (idx >> 7) & 7;
            int lane = (idx >> 2) & 31, r = idx & 3;
            int m = mt * 16 + (r & 1) * 8 + (lane >> 2);
            int k0 = s * 16 + ((r >> 1) & 1) * 8 + (lane & 3) * 2;
            float x0 = (m < OO) ? w2[m * 128 + k0] : 0.f;
            float x1 = (m < OO) ? w2[m * 128 + k0 + 1] : 0.f;
            g_W2[idx] = pack2h(x0, x1);
        }
    }
}

// ---------------- K2: conditioning vectors (embedding gather fused) -------------
__global__ void __launch_bounds__(256) k_H(
    const int* __restrict__ gin, const float* __restrict__ emb,
    const float* __restrict__ wlf, const float* __restrict__ blf,
    const float* __restrict__ wlg, const float* __restrict__ blg)
{
    __shared__ float sE[GEGE * 4];
    __shared__ float sR[256 * 4];
    int i = blockIdx.x;
    int b0 = blockIdx.y * 4;
    int tid = threadIdx.x;

    for (int idx = tid; idx < GEGE * 4; idx += 256) {
        int k = idx >> 2, bj = idx & 3;
        int g = k >> 7, e = k & 127;
        int tok = gin[(b0 + bj) * GG + g];
        sE[idx] = (tok == 0) ? 0.f : emb[tok * EE + e];
    }
    __syncthreads();

    int row = tid & 127;
    int half = tid >> 7;
    int c = row & 63;
    bool isf = row < 64;
    const float* w = (isf ? wlf : wlg) + ((size_t)i * CC + c) * GEGE + half * 512;
    const float* ep = sE + half * 512 * 4;

    float a0 = 0.f, a1 = 0.f, a2 = 0.f, a3 = 0.f;
    #pragma unroll 4
    for (int k = 0; k < 512; k += 4) {
        float4 wv = *(const float4*)(w + k);
        float4 e0 = *(const float4*)(ep + k * 4);
        float4 e1 = *(const float4*)(ep + k * 4 + 4);
        float4 e2 = *(const float4*)(ep + k * 4 + 8);
        float4 e3 = *(const float4*)(ep + k * 4 + 12);
        a0 = fmaf(wv.x, e0.x, a0); a1 = fmaf(wv.x, e0.y, a1);
        a2 = fmaf(wv.x, e0.z, a2); a3 = fmaf(wv.x, e0.w, a3);
        a0 = fmaf(wv.y, e1.x, a0); a1 = fmaf(wv.y, e1.y, a1);
        a2 = fmaf(wv.y, e1.z, a2); a3 = fmaf(wv.y, e1.w, a3);
        a0 = fmaf(wv.z, e2.x, a0); a1 = fmaf(wv.z, e2.y, a1);
        a2 = fmaf(wv.z, e2.z, a2); a3 = fmaf(wv.z, e2.w, a3);
        a0 = fmaf(wv.w, e3.x, a0); a1 = fmaf(wv.w, e3.y, a1);
        a2 = fmaf(wv.w, e3.z, a2); a3 = fmaf(wv.w, e3.w, a3);
    }
    *(float4*)&sR[tid * 4] = make_float4(a0, a1, a2, a3);
    __syncthreads();
    if (tid < 128) {
        float4 lo = *(const float4*)&sR[tid * 4];
        float4 hi = *(const float4*)&sR[(tid + 128) * 4];
        float bias = (isf ? blf : blg)[i * CC + c];
        float* dst = (isf ? g_HF : g_HG);
        dst[((size_t)i * BB + b0 + 0) * CC + c] = lo.x + hi.x + bias;
        dst[((size_t)i * BB + b0 + 1) * CC + c] = lo.y + hi.y + bias;
        dst[((size_t)i * BB + b0 + 2) * CC + c] = lo.z + hi.z + bias;
        dst[((size_t)i * BB + b0 + 3) * CC + c] = lo.w + hi.w + bias;
    }
}

// ---------------- K3: initial residual -> split slot format ----------------------
__global__ void __launch_bounds__(256) k_init(
    const int* __restrict__ tok, const float* __restrict__ b_causal)
{
    __shared__ float sM0[VV * CC], sM1[VV * CC], sb[CC];
    int tid = threadIdx.x;
    for (int i = tid; i < VV * CC; i += 256) { sM0[i] = g_M0[i]; sM1[i] = g_M1[i]; }
    if (tid < CC) sb[tid] = b_causal[tid];
    __syncthreads();
    int b = blockIdx.y, tt0 = blockIdx.x * 64;
    const int* tb = tok + b * LL;
    uint2* oH = rowsH(0, b);
    uint2* oL = rowsL(0, b);
    for (int idx = tid; idx < 1024; idx += 256) {
        int tl = idx >> 4, s = idx & 15;
        int qc = ((s >> 2) << 3) + (s & 3);
        int c0 = 2 * qc;
        int t = tt0 + tl;
        int v1 = tb[t] * CC;
        float r[4];
        r[0] = sM1[v1 + c0] + sb[c0];
        r[1] = sM1[v1 + c0 + 1] + sb[c0 + 1];
        r[2] = sM1[v1 + c0 + 8] + sb[c0 + 8];
        r[3] = sM1[v1 + c0 + 9] + sb[c0 + 9];
        if (t > 0) {
            int v0 = tb[t - 1] * CC;
            r[0] += sM0[v0 + c0];
            r[1] += sM0[v0 + c0 + 1];
            r[2] += sM0[v0 + c0 + 8];
            r[3] += sM0[v0 + c0 + 9];
        }
        u32 h1, l1, h2, l2;
        split2h(r[0], r[1], h1, l1);
        split2h(r[2], r[3], h2, l2);
        oH[t * 16 + s] = make_uint2(h1, h2);
        oL[t * 16 + s] = make_uint2(l1, l2);
    }
}

// ---------------- K4: dilated residual layer (occupancy 3) ----------------------
__global__ void __launch_bounds__(256, 3) k_layer_tc(
    const float* __restrict__ b_f, const float* __restrict__ b_g,
    const float* __restrict__ b_res,
    int layer, int d, int in_sel, int out_sel)
{
    extern __shared__ u32 smem_u[];
    uint4* Xq  = (uint4*)smem_u;                   // 64 x XQ4
    uint2* XfL = (uint2*)(smem_u + 5120);          // [t][j] pitch 16
    u32*   sZ  = smem_u + 7168;                    // [t][cpair] pitch ZP32
    float* SK  = (float*)(smem_u + 9472);          // 64 x 68
    float* sBF = (float*)(smem_u + 13824);         // 64
    float* sBG = sBF + 64;
    float* sBR = sBG + 64;

    int tid = threadIdx.x;
    int lane = tid & 31;
    int w = tid >> 5;
    int b = blockIdx.y;
    int tt0 = blockIdx.x * 64;
    int r = lane & 3, tb = lane >> 2;

    if (tid < 64)
        sBF[tid] = b_f[layer * CC + tid] + g_HF[((size_t)layer * BB + b) * CC + tid];
    else if (tid < 128) {
        int c = tid - 64;
        sBG[c] = b_g[layer * CC + c] + g_HG[((size_t)layer * BB + b) * CC + c];
    } else if (tid < 192) {
        int c = tid - 128;
        sBR[c] = b_res[layer * CC + c];
    }

    // ---- build Xq: prev-hi in .xy, cur-hi in .zw; cur-lo in XfL ----
    const uint2* iH = rowsH(in_sel, b);
    const uint2* iL = rowsL(in_sel, b);
    #pragma unroll
    for (int it = 0; it < 4; it++) {
        int id = it * 256 + tid;
        int t = id >> 4, j = id & 15;
        int gtp = tt0 + t - d;
        int gtc = tt0 + t;
        uint2 P = make_uint2(0u, 0u);
        if (gtp >= 0) P = iH[gtp * 16 + j];
        uint2 C = iH[gtc * 16 + j];
        Xq[t * XQ4 + j] = make_uint4(P.x, P.y, C.x, C.y);
        XfL[t * 16 + j] = iL[gtc * 16 + j];
    }
    __syncthreads();                      // (1) X ready

    // ---- GEMM1: warp mg does f-tile mg and g-tile 4+mg ----
    int mg = w & 3, ng = w >> 2;
    float acc[2][4][4];
    #pragma unroll
    for (int mi = 0; mi < 2; mi++)
        #pragma unroll
        for (int j = 0; j < 4; j++)
            #pragma unroll
            for (int rr = 0; rr < 4; rr++) acc[mi][j][rr] = 0.f;

    const uint4* WFb = (const uint4*)(g_WF + (size_t)layer * 8192);
    const uint4* WFf = WFb + mg * 256;
    const uint4* WFg = WFb + (4 + mg) * 256;
    uint4 A[2][2][2];
    A[0][0][0] = WFf[lane];           A[0][0][1] = WFf[4 * 32 + lane];
    A[0][1][0] = WFg[lane];           A[0][1][1] = WFg[4 * 32 + lane];
    #pragma unroll
    for (int s = 0; s < 4; s++) {
        int cur = s & 1, nxt = cur ^ 1;
        if (s < 3) {
            A[nxt][0][0] = WFf[(s + 1) * 32 + lane];
            A[nxt][0][1] = WFf[(s + 5) * 32 + lane];
            A[nxt][1][0] = WFg[(s + 1) * 32 + lane];
            A[nxt][1][1] = WFg[(s + 5) * 32 + lane];
        }
        uint4 B0 = Xq[(ng * 32 + 0 + tb) * XQ4 + s * 4 + r];
        uint4 B1 = Xq[(ng * 32 + 8 + tb) * XQ4 + s * 4 + r];
        uint4 B2 = Xq[(ng * 32 + 16 + tb) * XQ4 + s * 4 + r];
        uint4 B3 = Xq[(ng * 32 + 24 + tb) * XQ4 + s * 4 + r];
        #pragma unroll
        for (int mi = 0; mi < 2; mi++) {
            uint4 a0 = A[cur][mi][0];
            uint4 a1 = A[cur][mi][1];
            mma16816h(acc[mi][0], a0.x, a0.y, a0.z, a0.w, B0.x, B0.y);
            mma16816h(acc[mi][0], a1.x, a1.y, a1.z, a1.w, B0.z, B0.w);
            mma16816h(acc[mi][1], a0.x, a0.y, a0.z, a0.w, B1.x, B1.y);
            mma16816h(acc[mi][1], a1.x, a1.y, a1.z, a1.w, B1.z, B1.w);
            mma16816h(acc[mi][2], a0.x, a0.y, a0.z, a0.w, B2.x, B2.y);
            mma16816h(acc[mi][2], a1.x, a1.y, a1.z, a1.w, B2.z, B2.w);
            mma16816h(acc[mi][3], a0.x, a0.y, a0.z, a0.w, B3.x, B3.y);
            mma16816h(acc[mi][3], a1.x, a1.y, a1.z, a1.w, B3.z, B3.w);
        }
    }

    // ---- register-resident gated activation -> z halves ----
    {
        int gr = lane >> 2, tq = 2 * (lane & 3);
        int c1 = mg * 16 + gr;
        int c2 = c1 + 8;
        float bf1 = sBF[c1], bf2 = sBF[c2];
        float bg1 = sBG[c1], bg2 = sBG[c2];
        u16* sZh = (u16*)sZ;
        #pragma unroll
        for (int j = 0; j < 4; j++) {
            int t0 = ng * 32 + j * 8 + tq;
            #pragma unroll
            for (int rr = 0; rr < 4; rr++) {
                int c = (rr < 2) ? c1 : c2;
                float bf = (rr < 2) ? bf1 : bf2;
                float bg = (rr < 2) ? bg1 : bg2;
                int t = t0 + (rr & 1);
                float z = fast_tanh(acc[0][j][rr] + bf) *
                          fast_sigmoid(acc[1][j][rr] + bg);
                __half zh = __float2half_rn(z);
                sZh[t * (ZP32 * 2) + c] = *(u16*)&zh;
            }
        }
    }
    __syncthreads();                      // (2) z ready

    // ---- GEMM2 ----
    int mg2 = w & 1, ng2 = w >> 1;
    float acc2[2][2][4];
    #pragma unroll
    for (int mi = 0; mi < 2; mi++)
        #pragma unroll
        for (int j = 0; j < 2; j++)
            #pragma unroll
            for (int rr = 0; rr < 4; rr++) acc2[mi][j][rr] = 0.f;

    const uint4* WRp = (const uint4*)(g_WR + (size_t)layer * 2048) + (mg2 * 2) * 128;
    uint4 A2[2][2];
    #pragma unroll
    for (int mi = 0; mi < 2; mi++) A2[0][mi] = WRp[mi * 128 + lane];
    #pragma unroll
    for (int s = 0; s < 4; s++) {
        int cur = s & 1, nxt = cur ^ 1;
        if (s < 3) {
            #pragma unroll
            for (int mi = 0; mi < 2; mi++)
                A2[nxt][mi] = WRp[mi * 128 + (s + 1) * 32 + lane];
        }
        int q = s * 8 + r;
        int ta = ng2 * 16 + tb;
        u32 b00 = sZ[ta * ZP32 + q];
        u32 b01 = sZ[ta * ZP32 + q + 4];
        u32 b10 = sZ[(ta + 8) * ZP32 + q];
        u32 b11 = sZ[(ta + 8) * ZP32 + q + 4];
        #pragma unroll
        for (int mi = 0; mi < 2; mi++) {
            uint4 Ah = A2[cur][mi];
            mma16816h(acc2[mi][0], Ah.x, Ah.y, Ah.z, Ah.w, b00, b01);
            mma16816h(acc2[mi][1], Ah.x, Ah.y, Ah.z, Ah.w, b10, b11);
        }
    }

    // ---- store skip ----
    {
        int gr = lane >> 2, tq = 2 * (lane & 3);
        #pragma unroll
        for (int mi = 0; mi < 2; mi++)
            #pragma unroll
            for (int j = 0; j < 2; j++) {
                int m = mg2 * 32 + mi * 16 + gr;
                int t = ng2 * 16 + j * 8 + tq;
                SK[t * 68 + m]       = acc2[mi][j][0];
                SK[(t + 1) * 68 + m] = acc2[mi][j][1];
                SK[t * 68 + m + 8]       = acc2[mi][j][2];
                SK[(t + 1) * 68 + m + 8] = acc2[mi][j][3];
            }
    }
    __syncthreads();                      // (3) SK ready

    // ---- epilogue ----
    uint2* oH = rowsH(out_sel, b);
    uint2* oL = rowsL(out_sel, b);
    #pragma unroll
    for (int it = 0; it < 4; it++) {
        int id = it * 256 + tid;
        int t = id >> 4, s = id & 15;
        int qc = ((s >> 2) << 3) + (s & 3);
        int c0 = 2 * qc;
        uint2 H = *(const uint2*)(smem_u + t * (XQ4 * 4) + s * 4 + 2);
        uint2 L = XfL[t * 16 + s];
        float2 ra = recon2(H.x, L.x);
        float2 rb = recon2(H.y, L.y);
        float2 sk1 = *(const float2*)&SK[t * 68 + c0];
        float2 sk2 = *(const float2*)&SK[t * 68 + c0 + 8];
        float o0 = ra.x + sk1.x + sBR[c0];
        float o1 = ra.y + sk1.y + sBR[c0 + 1];
        float o2 = rb.x + sk2.x + sBR[c0 + 8];
        float o3 = rb.y + sk2.y + sBR[c0 + 9];
        u32 h1, l1, h2, l2;
        split2h(o0, o1, h1, l1);
        split2h(o2, o3, h2, l2);
        int gt = tt0 + t;
        oH[gt * 16 + s] = make_uint2(h1, h2);
        oL[gt * 16 + s] = make_uint2(l1, l2);
    }
}

// ---------------- K5: head (hi-only MMAs) ----------------------------------------
__global__ void __launch_bounds__(256, 2) k_final_tc(
    const float* __restrict__ b1, const float* __restrict__ b2,
    float* __restrict__ out)
{
    extern __shared__ u32 smem_u[];
    u32* XH = smem_u;                 // 64 x 36 u32
    float* Dsm = (float*)smem_u;      // overlay: 128 x 68 f32
    u32* HH = smem_u + 8704;          // 64 x 68 u32

    int tid = threadIdx.x;
    int lane = tid & 31;
    int w = tid >> 5;
    int b = blockIdx.y;
    int tt0 = blockIdx.x * 64;
    int tb = lane >> 2;

    const uint2* aH = rowsH(1, b);
    const uint2* aL = rowsL(1, b);
    const uint2* zH = rowsH(0, b);
    const uint2* zL = rowsL(0, b);
    #pragma unroll
    for (int it = 0; it < 4; it++) {
        int id = it * 256 + tid;
        int t = id >> 4, s = id & 15;
        int gt = tt0 + t;
        uint2 AH = aH[gt * 16 + s], AL = aL[gt * 16 + s];
        uint2 ZH0 = zH[gt * 16 + s], ZL0 = zL[gt * 16 + s];
        float2 a1 = recon2(AH.x, AL.x), a2 = recon2(AH.y, AL.y);
        float2 z1 = recon2(ZH0.x, ZL0.x), z2 = recon2(ZH0.y, ZL0.y);
        float s0 = fmaxf(a1.x - z1.x, 0.f), s1 = fmaxf(a1.y - z1.y, 0.f);
        float s2 = fmaxf(a2.x - z2.x, 0.f), s3 = fmaxf(a2.y - z2.y, 0.f);
        int q = ((s >> 2) << 3) + (s & 3);
        int o = t * 36 + q;
        XH[o] = pack2h(s0, s1);
        XH[o + 4] = pack2h(s2, s3);
    }
    __syncthreads();

    float acc[8][4];
    #pragma unroll
    for (int j = 0; j < 8; j++)
        #pragma unroll
        for (int rr = 0; rr < 4; rr++) acc[j][rr] = 0.f;

    const uint4* W1p = (const uint4*)(g_W1 + w * 512);
    #pragma unroll
    for (int s = 0; s < 4; s++) {
        uint4 Ah = W1p[s * 32 + lane];
        int kb = s * 8 + (lane & 3);
        #pragma unroll
        for (int j = 0; j < 8; j++) {
            int base = (j * 8 + tb) * 36 + kb;
            mma16816h(acc[j], Ah.x, Ah.y, Ah.z, Ah.w, XH[base], XH[base + 4]);
        }
    }
    __syncthreads();

    {
        int g = lane >> 2, tq = 2 * (lane & 3);
        int m = w * 16 + g;
        #pragma unroll
        for (int j = 0; j < 8; j++) {
            int t = j * 8 + tq;
            *(float2*)&Dsm[m * 68 + t] = make_float2(acc[j][0], acc[j][1]);
            *(float2*)&Dsm[(m + 8) * 68 + t] = make_float2(acc[j][2], acc[j][3]);
        }
    }
    __syncthreads();

    #pragma unroll
    for (int it = 0; it < 16; it++) {
        int id = it * 256 + tid;
        int mp = id & 63, t = id >> 6;
        float h0 = fmaxf(Dsm[(2 * mp) * 68 + t] + b1[2 * mp], 0.f);
        float h1 = fmaxf(Dsm[(2 * mp + 1) * 68 + t] + b1[2 * mp + 1], 0.f);
        HH[t * 68 + mp] = pack2h(h0, h1);
    }
    __syncthreads();

    int mt = w & 1;
    float acc2[2][4];
    #pragma unroll
    for (int j = 0; j < 2; j++)
        #pragma unroll
        for (int rr = 0; rr < 4; rr++) acc2[j][rr] = 0.f;

    const uint4* W2p = (const uint4*)(g_W2 + mt * 1024);
    #pragma unroll
    for (int s = 0; s < 8; s++) {
        uint4 Ah = W2p[s * 32 + lane];
        int kb = s * 8 + (lane & 3);
        #pragma unroll
        for (int j = 0; j < 2; j++) {
            int nblk = (w >> 1) * 2 + j;
            int base = (nblk * 8 + tb) * 68 + kb;
            mma16816h(acc2[j], Ah.x, Ah.y, Ah.z, Ah.w, HH[base], HH[base + 4]);
        }
    }

    {
        int m = mt * 16 + (lane >> 2);
        #pragma unroll
        for (int j = 0; j < 2; j++) {
            int nblk = (w >> 1) * 2 + j;
            int t = tt0 + nblk * 8 + 2 * (lane & 3);
            int o1 = m, o2 = m + 8;
            *(float2*)(out + ((size_t)b * OO + o1) * LL + t) =
                make_float2(acc2[j][0] + b2[o1], acc2[j][1] + b2[o1]);
            if (o2 < OO)
                *(float2*)(out + ((size_t)b * OO + o2) * LL + t) =
                    make_float2(acc2[j][2] + b2[o2], acc2[j][3] + b2[o2]);
        }
    }
}

// ---------------- launch ----------------------------------------------------------
extern "C" void kernel_launch(void* const* d_in, const int* in_sizes, int n_in,
                              void* d_out, int out_size)
{
    const int*   in_tok = (const int*)d_in[0];
    const int*   g_tok  = (const int*)d_in[1];
    const float* emb    = (const float*)d_in[2];
    const float* wc     = (const float*)d_in[3];
    const float* bc     = (const float*)d_in[4];
    const float* wf     = (const float*)d_in[5];
    const float* bf     = (const float*)d_in[6];
    const float* wg     = (const float*)d_in[7];
    const float* bg     = (const float*)d_in[8];
    const float* wlf    = (const float*)d_in[9];
    const float* blf    = (const float*)d_in[10];
    const float* wlg    = (const float*)d_in[11];
    const float* blg    = (const float*)d_in[12];
    const float* wres   = (const float*)d_in[13];
    const float* bres   = (const float*)d_in[14];
    const float* w1     = (const float*)d_in[15];
    const float* b1     = (const float*)d_in[16];
    const float* w2     = (const float*)d_in[17];
    const float* b2     = (const float*)d_in[18];
    float* out = (float*)d_out;

    const int LAYER_SMEM = 14016 * 4;   // 56064 B (3 blocks/SM)
    const int FINAL_SMEM = 13056 * 4;   // 52224 B
    cudaFuncSetAttribute(k_layer_tc, cudaFuncAttributeMaxDynamicSharedMemorySize, LAYER_SMEM);
    cudaFuncSetAttribute(k_final_tc, cudaFuncAttributeMaxDynamicSharedMemorySize, FINAL_SMEM);

    k_precompute_M<<<VV, 64>>>(emb, wc);
    k_prep<<<NDND + 1, 256>>>(wf, wg, wres, w1, w2);
    k_H<<<dim3(NDND, 16), 256>>>(g_tok, emb, wlf, blf, wlg, blg);
    k_init<<<dim3(LL / 64, BB), 256>>>(in_tok, bc);
    for (int i = 0; i < NDND; i++) {
        int d = 2 << i;
        int out_sel = (i % 2 == 0) ? 1 : 2;           // layer 8 -> sel 1
        int in_sel  = (i == 0) ? 0 : ((i % 2 == 0) ? 2 : 1);
        k_layer_tc<<<dim3(LL / 64, BB), 256, LAYER_SMEM>>>(
            bf, bg, bres, i, d, in_sel, out_sel);
    }
    k_final_tc<<<dim3(LL / 64, BB), 256, FINAL_SMEM>>>(b1, b2, out);
}